// round 11
// baseline (speedup 1.0000x reference)
#include <cuda_runtime.h>
#include <cuda_bf16.h>
#include <math.h>
#include <stdint.h>

// Problem constants
#define Bv 2
#define Sv 2048
#define Dv 1024
#define Hv 16
#define DKv 64
#define Nv (Bv * Sv)     // 4096 rows
#define BHv (Bv * Hv)    // 32
#define NSS 16           // super-slabs of 64 K-columns

// ---------------------------------------------------------------------------
// Scratch (device globals — no cudaMalloc allowed). Hi/lo stored separately.
// ---------------------------------------------------------------------------
__device__ __nv_bfloat16 g_xh[(size_t)Nv * Dv];
__device__ __nv_bfloat16 g_xl[(size_t)Nv * Dv];
__device__ __nv_bfloat16 g_ash[(size_t)Nv * Dv];   // attention out hi
__device__ __nv_bfloat16 g_asl[(size_t)Nv * Dv];   // attention out lo
__device__ __nv_bfloat16 g_wh[4][(size_t)Dv * Dv];
__device__ __nv_bfloat16 g_wl[4][(size_t)Dv * Dv];
__device__ __nv_bfloat16 g_qh[(size_t)BHv * Sv * DKv];    // [bh][s][dk]
__device__ __nv_bfloat16 g_ql[(size_t)BHv * Sv * DKv];
__device__ __nv_bfloat16 g_kh[(size_t)BHv * Sv * DKv];
__device__ __nv_bfloat16 g_kl[(size_t)BHv * Sv * DKv];
__device__ __nv_bfloat16 g_vsh[(size_t)BHv * Sv * DKv];   // V split, s-major
__device__ __nv_bfloat16 g_vsl[(size_t)BHv * Sv * DKv];
__device__ __nv_bfloat16 g_vh[(size_t)BHv * DKv * Sv];    // [bh][dk][s]
__device__ __nv_bfloat16 g_vl[(size_t)BHv * DKv * Sv];

__device__ __forceinline__ uint32_t smem_to_u32(const void* p) {
    uint32_t a;
    asm("{ .reg .u64 t; cvta.to.shared.u64 t, %1; cvt.u32.u64 %0, t; }"
        : "=r"(a) : "l"(p));
    return a;
}
#define SW128(off) ((off) ^ (((off) >> 3) & 0x70))

__device__ __forceinline__ void ldm_x4(uint32_t* r, uint32_t addr) {
    asm volatile("ldmatrix.sync.aligned.m8n8.x4.shared.b16 {%0,%1,%2,%3}, [%4];"
        : "=r"(r[0]), "=r"(r[1]), "=r"(r[2]), "=r"(r[3]) : "r"(addr));
}
__device__ __forceinline__ void mma_16816(float* d, const uint32_t* a,
                                          const uint32_t* b) {
    asm volatile(
        "mma.sync.aligned.m16n8k16.row.col.f32.bf16.bf16.f32 "
        "{%0,%1,%2,%3}, {%4,%5,%6,%7}, {%8,%9}, {%0,%1,%2,%3};"
        : "+f"(d[0]), "+f"(d[1]), "+f"(d[2]), "+f"(d[3])
        : "r"(a[0]), "r"(a[1]), "r"(a[2]), "r"(a[3]), "r"(b[0]), "r"(b[1]));
}
__device__ __forceinline__ void cpa16(uint32_t dst, const void* src) {
    asm volatile("cp.async.cg.shared.global [%0], [%1], 16;"
        :: "r"(dst), "l"(src));
}
#define CP_COMMIT() asm volatile("cp.async.commit_group;" ::: "memory")
#define CP_WAIT(n)  asm volatile("cp.async.wait_group %0;" :: "n"(n) : "memory")

// split a float pair into hi/lo bf16x2 words
__device__ __forceinline__ void split2(float a, float b, uint32_t& h, uint32_t& l) {
    __nv_bfloat162 hp = __floats2bfloat162_rn(a, b);
    float r0 = __bfloat162float(hp.x), r1 = __bfloat162float(hp.y);
    __nv_bfloat162 lp = __floats2bfloat162_rn(a - r0, b - r1);
    h = *(uint32_t*)&hp;
    l = *(uint32_t*)&lp;
}

// ---------------------------------------------------------------------------
// Split fp32 -> separate hi/lo bf16 arrays (same [r][1024] layout)
// ---------------------------------------------------------------------------
__device__ __forceinline__ void split_body(
    const float* __restrict__ src, __nv_bfloat16* __restrict__ dh,
    __nv_bfloat16* __restrict__ dl, size_t e0)
{
    float4 v = *(const float4*)(src + e0);
    uint2 hu, lu;
    split2(v.x, v.y, hu.x, lu.x);
    split2(v.z, v.w, hu.y, lu.y);
    *(uint2*)(dh + e0) = hu;
    *(uint2*)(dl + e0) = lu;
}

__global__ __launch_bounds__(256) void xsplit_kernel(const float* __restrict__ x)
{
    size_t e0 = ((size_t)blockIdx.x * 256 + threadIdx.x) * 4;
    split_body(x, g_xh, g_xl, e0);
}

__global__ __launch_bounds__(256) void wsplit_kernel(
    const float* __restrict__ w0, const float* __restrict__ w1,
    const float* __restrict__ w2, const float* __restrict__ w3)
{
    int i = blockIdx.x >> 10;
    const float* src = (i == 0) ? w0 : (i == 1) ? w1 : (i == 2) ? w2 : w3;
    size_t e0 = ((size_t)(blockIdx.x & 1023) * 256 + threadIdx.x) * 4;
    split_body(src, g_wh[i], g_wl[i], e0);
}

// ---------------------------------------------------------------------------
// Split-term GEMM: Y = Ah*Bh + Ah*Bl + Al*Bh over K=1024 in 16 super-slabs.
// Each super-slab loads 4 sub-slabs (Ah,Al,Bh,Bl; 128x64 each = 64KB/stage),
// computes 3 products from them. 3-stage cp.async, one sync per super-slab.
// mode: 0 = fp32 store; 1 = K RoPE split; 2 = Q RoPE+1/8 split; 3 = V split.
// ---------------------------------------------------------------------------
__device__ __forceinline__ void gemm_load_ss(
    const __nv_bfloat16* __restrict__ Ah, const __nv_bfloat16* __restrict__ Al,
    const __nv_bfloat16* __restrict__ Bh, const __nv_bfloat16* __restrict__ Bl,
    uint32_t bufu, int ss, int tid)
{
    #pragma unroll
    for (int kk = 0; kk < 4; ++kk) {
        int idx = kk * 256 + tid;          // 0..1023
        int r = idx >> 3, c = idx & 7;
        size_t goff = (size_t)r * Dv + ss * 64 + c * 8;
        uint32_t so = SW128((uint32_t)(r * 128 + c * 16));
        cpa16(bufu + so,         Ah + goff);
        cpa16(bufu + 16384 + so, Al + goff);
        cpa16(bufu + 32768 + so, Bh + goff);
        cpa16(bufu + 49152 + so, Bl + goff);
    }
}

__device__ __forceinline__ void gemm_tile(
    const __nv_bfloat16* __restrict__ Ah, const __nv_bfloat16* __restrict__ Al,
    const __nv_bfloat16* __restrict__ Bh, const __nv_bfloat16* __restrict__ Bl,
    const int* __restrict__ tp, int mode, int m0, int e0, uint32_t sbu,
    float* __restrict__ Y, __nv_bfloat16* __restrict__ dh,
    __nv_bfloat16* __restrict__ dl)
{
    const int tid = threadIdx.x;
    const int wid = tid >> 5;
    const int lane = tid & 31;
    const int wm = wid >> 1;
    const int wn = wid & 1;
    const int g2 = lane >> 2;
    const int t4 = lane & 3;
    const int lrow = lane & 15;
    const int lkoff = ((lane >> 4) & 1) * 16;

    float acc[2][8][4];
    #pragma unroll
    for (int i = 0; i < 2; ++i)
        #pragma unroll
        for (int j = 0; j < 8; ++j)
            #pragma unroll
            for (int k = 0; k < 4; ++k) acc[i][j][k] = 0.f;

    // prologue: super-slabs 0,1 -> stages 0,1
    gemm_load_ss(Ah, Al, Bh, Bl, sbu, 0, tid);
    CP_COMMIT();
    gemm_load_ss(Ah, Al, Bh, Bl, sbu + 65536, 1, tid);
    CP_COMMIT();

    int cc = 0;   // current stage = ss % 3
    for (int ss = 0; ss < NSS; ++ss) {
        if (ss + 1 < NSS) { CP_WAIT(1); } else { CP_WAIT(0); }
        __syncthreads();
        if (ss + 2 < NSS) {
            int nb = cc + 2; if (nb >= 3) nb -= 3;
            gemm_load_ss(Ah, Al, Bh, Bl, sbu + (uint32_t)(nb * 65536),
                         ss + 2, tid);
            CP_COMMIT();
        }

        const uint32_t pAh = sbu + (uint32_t)(cc * 65536);
        const uint32_t pAl = pAh + 16384;
        const uint32_t pBh = pAh + 32768;
        const uint32_t pBl = pAh + 49152;
        #pragma unroll
        for (int ks = 0; ks < 4; ++ks) {
            const uint32_t kbyte = (uint32_t)(ks * 32 + lkoff);
            uint32_t ahf[2][4], alf[2][4], bhf[4][4], blf[4][4];
            #pragma unroll
            for (int am = 0; am < 2; ++am) {
                uint32_t off =
                    SW128((uint32_t)((wm * 32 + am * 16 + lrow) * 128) + kbyte);
                ldm_x4(ahf[am], pAh + off);
                ldm_x4(alf[am], pAl + off);
            }
            #pragma unroll
            for (int bn = 0; bn < 4; ++bn) {
                uint32_t off =
                    SW128((uint32_t)((wn * 64 + bn * 16 + lrow) * 128) + kbyte);
                ldm_x4(bhf[bn], pBh + off);
                ldm_x4(blf[bn], pBl + off);
            }
            #pragma unroll
            for (int am = 0; am < 2; ++am)
                #pragma unroll
                for (int bn = 0; bn < 4; ++bn) {
                    uint32_t bh0[2] = {bhf[bn][0], bhf[bn][2]};
                    uint32_t bh1[2] = {bhf[bn][1], bhf[bn][3]};
                    uint32_t bl0[2] = {blf[bn][0], blf[bn][2]};
                    uint32_t bl1[2] = {blf[bn][1], blf[bn][3]};
                    // Ah*Bh + Ah*Bl + Al*Bh
                    mma_16816(acc[am][bn * 2],     ahf[am], bh0);
                    mma_16816(acc[am][bn * 2 + 1], ahf[am], bh1);
                    mma_16816(acc[am][bn * 2],     ahf[am], bl0);
                    mma_16816(acc[am][bn * 2 + 1], ahf[am], bl1);
                    mma_16816(acc[am][bn * 2],     alf[am], bh0);
                    mma_16816(acc[am][bn * 2 + 1], alf[am], bh1);
                }
        }
        ++cc; if (cc == 3) cc = 0;
    }

    const float qs = (mode == 2) ? 0.125f : 1.0f;
    const float LTH = 0.2878231366242557f;   // ln(10000)/32
    #pragma unroll
    for (int am = 0; am < 2; ++am) {
        #pragma unroll
        for (int half = 0; half < 2; ++half) {
            int m = m0 + wm * 32 + am * 16 + g2 + half * 8;
            int sr = m & (Sv - 1);
            float pos = (mode == 1 || mode == 2) ? (float)tp[sr] : 0.f;
            #pragma unroll
            for (int bn = 0; bn < 8; ++bn) {
                int e = e0 + wn * 64 + bn * 8 + t4 * 2;
                float d0 = acc[am][bn][half * 2];
                float d1 = acc[am][bn][half * 2 + 1];
                if (mode == 1 || mode == 2) {
                    int p = (e & (DKv - 1)) >> 1;
                    float inv = expf(-LTH * (float)p);
                    float sn, cs;
                    sincosf(pos * inv, &sn, &cs);
                    float o0 = (cs * d0 - sn * d1) * qs;
                    float o1 = (sn * d0 + cs * d1) * qs;
                    d0 = o0; d1 = o1;
                }
                if (mode == 0) {
                    *(float2*)(Y + (size_t)m * Dv + e) = make_float2(d0, d1);
                } else {
                    int bh = (m >> 11) * Hv + (e >> 6);
                    int dk = e & (DKv - 1);
                    size_t idx = ((size_t)bh * Sv + sr) * DKv + dk;
                    uint32_t h, l;
                    split2(d0, d1, h, l);
                    *(uint32_t*)(dh + idx) = h;
                    *(uint32_t*)(dl + idx) = l;
                }
            }
        }
    }
}

// Fused QKV projection: grid (24, 32); region = blockIdx.x >> 3 (0=Q,1=K,2=V)
__global__ __launch_bounds__(256, 1) void gemm_qkv(const int* __restrict__ tp)
{
    extern __shared__ char smraw[];
    uint32_t su = smem_to_u32(smraw);
    uint32_t sbu = (su + 1023u) & ~1023u;

    const int region = blockIdx.x >> 3;
    const int e0 = (blockIdx.x & 7) * 128;
    const int m0 = blockIdx.y * 128;
    const __nv_bfloat16* Ah = g_xh + (size_t)m0 * Dv;
    const __nv_bfloat16* Al = g_xl + (size_t)m0 * Dv;
    const __nv_bfloat16* Bh = g_wh[region] + (size_t)e0 * Dv;
    const __nv_bfloat16* Bl = g_wl[region] + (size_t)e0 * Dv;
    __nv_bfloat16* dh = (region == 0) ? g_qh : (region == 1) ? g_kh : g_vsh;
    __nv_bfloat16* dl = (region == 0) ? g_ql : (region == 1) ? g_kl : g_vsl;
    const int mode = (region == 0) ? 2 : (region == 1) ? 1 : 3;
    gemm_tile(Ah, Al, Bh, Bl, tp, mode, m0, e0, sbu, (float*)0, dh, dl);
}

// Output projection: grid (8, 32)
__global__ __launch_bounds__(256, 1) void gemm_o(float* __restrict__ out)
{
    extern __shared__ char smraw[];
    uint32_t su = smem_to_u32(smraw);
    uint32_t sbu = (su + 1023u) & ~1023u;

    const int e0 = blockIdx.x * 128;
    const int m0 = blockIdx.y * 128;
    gemm_tile(g_ash + (size_t)m0 * Dv, g_asl + (size_t)m0 * Dv,
              g_wh[3] + (size_t)e0 * Dv, g_wl[3] + (size_t)e0 * Dv,
              (const int*)0, 0, m0, e0, sbu, out,
              (__nv_bfloat16*)0, (__nv_bfloat16*)0);
}

// ---------------------------------------------------------------------------
// bf16 transpose: g_vsh/g_vsl [bh][s][64] -> g_vh/g_vl [bh][dk][s]
// ---------------------------------------------------------------------------
__global__ __launch_bounds__(256) void v_prep2()
{
    __shared__ __nv_bfloat16 sv[64][72];
    const int tid = threadIdx.x;
    const int st = blockIdx.x, bh = blockIdx.y;
    const int s0 = st * 64;

    #pragma unroll
    for (int pass = 0; pass < 2; ++pass) {
        const __nv_bfloat16* src = pass ? g_vsl : g_vsh;
        __nv_bfloat16* dst = pass ? g_vl : g_vh;
        if (pass) __syncthreads();
        #pragma unroll
        for (int p = 0; p < 2; ++p) {
            int idx = p * 256 + tid;         // 0..511 x 16B chunks
            int r = idx >> 3;
            int c = (idx & 7) * 8;
            *(uint4*)&sv[r][c] =
                *(const uint4*)(src + ((size_t)bh * Sv + s0 + r) * DKv + c);
        }
        __syncthreads();

        int dk = tid >> 2;
        int t0 = (tid & 3) * 16;
        uint32_t u[8];
        #pragma unroll
        for (int i = 0; i < 8; ++i) {
            __nv_bfloat162 p2 = {sv[t0 + 2*i][dk], sv[t0 + 2*i + 1][dk]};
            u[i] = *(uint32_t*)&p2;
        }
        size_t o = ((size_t)bh * DKv + dk) * Sv + s0 + t0;
        *(uint4*)(dst + o)     = make_uint4(u[0], u[1], u[2], u[3]);
        *(uint4*)(dst + o + 8) = make_uint4(u[4], u[5], u[6], u[7]);
    }
}

// ---------------------------------------------------------------------------
// Flash attention on mma.sync, 3-term split for QK^T and PV (proven R10 body;
// only the epilogue changed: writes g_ash/g_asl).
// ---------------------------------------------------------------------------
__device__ __forceinline__ void attn_load_tile(
    uint32_t sb, int bh, int j, int buf, int tid)
{
    const uint32_t oKh = 0, oKl = 16384, oVh = 32768, oVl = 49152;
    const char* kh = (const char*)(g_kh + ((size_t)bh * Sv + j * 64) * 64);
    const char* kl = (const char*)(g_kl + ((size_t)bh * Sv + j * 64) * 64);
    #pragma unroll
    for (int p = 0; p < 2; ++p) {
        int idx = p * 256 + tid;
        int r = idx >> 3, c = idx & 7;
        uint32_t so = SW128((uint32_t)(r * 128 + c * 16));
        uint32_t bo = (uint32_t)(buf * 8192);
        cpa16(sb + oKh + bo + so, kh + idx * 16);
        cpa16(sb + oKl + bo + so, kl + idx * 16);
        const char* vh = (const char*)(g_vh + ((size_t)bh * 64 + r) * Sv + j * 64);
        const char* vl = (const char*)(g_vl + ((size_t)bh * 64 + r) * Sv + j * 64);
        cpa16(sb + oVh + bo + so, vh + c * 16);
        cpa16(sb + oVl + bo + so, vl + c * 16);
    }
}

__global__ __launch_bounds__(256, 1) void attn_mma()
{
    extern __shared__ char smraw[];
    uint32_t su = smem_to_u32(smraw);
    uint32_t sb = (su + 1023u) & ~1023u;
    const uint32_t oKh = 0, oKl = 16384, oVh = 32768, oVl = 49152;

    const int tid = threadIdx.x;
    const int wid = tid >> 5, lane = tid & 31;
    const int g2 = lane >> 2, t4 = lane & 3;
    const int lrow = lane & 15;
    const int lkoff = ((lane >> 4) & 1) * 16;

    const int qt = gridDim.x - 1 - blockIdx.x;   // big tiles first
    const int h = blockIdx.y, b = blockIdx.z;
    const int bh = b * Hv + h;
    const int q0 = qt * 128;
    const int jmax = 2 * qt + 1;

    // --- stage Q through smem (reusing K buffer space), hoist frags to regs
    uint32_t qfh[4][4], qfl[4][4];
    {
        const char* qh = (const char*)(g_qh + ((size_t)bh * Sv + q0) * 64);
        const char* ql = (const char*)(g_ql + ((size_t)bh * Sv + q0) * 64);
        #pragma unroll
        for (int p = 0; p < 4; ++p) {
            int idx = p * 256 + tid;
            uint32_t so = SW128((uint32_t)(idx * 16));
            cpa16(sb + so,         qh + idx * 16);
            cpa16(sb + 16384 + so, ql + idx * 16);
        }
        CP_COMMIT();
        CP_WAIT(0);
        __syncthreads();
        #pragma unroll
        for (int ks = 0; ks < 4; ++ks) {
            uint32_t aoff =
                SW128((uint32_t)((wid * 16 + lrow) * 128 + ks * 32 + lkoff));
            ldm_x4(qfh[ks], sb + aoff);
            ldm_x4(qfl[ks], sb + 16384 + aoff);
        }
        __syncthreads();
        attn_load_tile(sb, bh, 0, 0, tid);
        CP_COMMIT();
    }

    float m0 = -1e30f, m1 = -1e30f, l0 = 0.f, l1 = 0.f;
    float oacc[8][4];
    #pragma unroll
    for (int i = 0; i < 8; ++i)
        #pragma unroll
        for (int c = 0; c < 4; ++c) oacc[i][c] = 0.f;

    for (int j = 0; j <= jmax; ++j) {
        const int cur = j & 1;
        CP_WAIT(0);
        __syncthreads();
        if (j < jmax) {
            attn_load_tile(sb, bh, j + 1, cur ^ 1, tid);
            CP_COMMIT();
        }

        // S = Qhi*Khi + Qhi*Klo + Qlo*Khi (Q frags in regs)
        float sacc[8][4];
        #pragma unroll
        for (int i = 0; i < 8; ++i)
            #pragma unroll
            for (int c = 0; c < 4; ++c) sacc[i][c] = 0.f;
        {
            const uint32_t kb = (uint32_t)(cur * 8192);
            const uint32_t khB = sb + oKh + kb, klB = sb + oKl + kb;
            #pragma unroll
            for (int ks = 0; ks < 4; ++ks) {
                uint32_t kbyte = (uint32_t)(ks * 32 + lkoff);
                #pragma unroll
                for (int bn4 = 0; bn4 < 4; ++bn4) {
                    uint32_t boff = SW128((uint32_t)((bn4 * 16 + lrow) * 128) + kbyte);
                    uint32_t bh_[4], bl_[4];
                    ldm_x4(bh_, khB + boff);
                    ldm_x4(bl_, klB + boff);
                    uint32_t bhl[2] = {bh_[0], bh_[2]}, bhh[2] = {bh_[1], bh_[3]};
                    uint32_t bll[2] = {bl_[0], bl_[2]}, blh[2] = {bl_[1], bl_[3]};
                    mma_16816(sacc[2 * bn4],     qfh[ks], bhl);
                    mma_16816(sacc[2 * bn4 + 1], qfh[ks], bhh);
                    mma_16816(sacc[2 * bn4],     qfh[ks], bll);
                    mma_16816(sacc[2 * bn4 + 1], qfh[ks], blh);
                    mma_16816(sacc[2 * bn4],     qfl[ks], bhl);
                    mma_16816(sacc[2 * bn4 + 1], qfl[ks], bhh);
                }
            }
        }

        if (j >= 2 * qt) {
            int r0 = q0 + wid * 16 + g2;
            #pragma unroll
            for (int bn = 0; bn < 8; ++bn) {
                int col = j * 64 + bn * 8 + 2 * t4;
                #pragma unroll
                for (int c = 0; c < 4; ++c) {
                    int row = r0 + ((c >= 2) ? 8 : 0);
                    if (col + (c & 1) > row) sacc[bn][c] = -1e30f;
                }
            }
        }

        float tm0 = -1e30f, tm1 = -1e30f;
        #pragma unroll
        for (int bn = 0; bn < 8; ++bn) {
            tm0 = fmaxf(tm0, fmaxf(sacc[bn][0], sacc[bn][1]));
            tm1 = fmaxf(tm1, fmaxf(sacc[bn][2], sacc[bn][3]));
        }
        tm0 = fmaxf(tm0, __shfl_xor_sync(0xffffffffu, tm0, 1));
        tm0 = fmaxf(tm0, __shfl_xor_sync(0xffffffffu, tm0, 2));
        tm1 = fmaxf(tm1, __shfl_xor_sync(0xffffffffu, tm1, 1));
        tm1 = fmaxf(tm1, __shfl_xor_sync(0xffffffffu, tm1, 2));
        float mn0 = fmaxf(m0, tm0), mn1 = fmaxf(m1, tm1);
        float sc0 = __expf(m0 - mn0), sc1 = __expf(m1 - mn1);
        float rs0 = 0.f, rs1 = 0.f;
        #pragma unroll
        for (int bn = 0; bn < 8; ++bn) {
            sacc[bn][0] = __expf(sacc[bn][0] - mn0);
            sacc[bn][1] = __expf(sacc[bn][1] - mn0);
            sacc[bn][2] = __expf(sacc[bn][2] - mn1);
            sacc[bn][3] = __expf(sacc[bn][3] - mn1);
            rs0 += sacc[bn][0] + sacc[bn][1];
            rs1 += sacc[bn][2] + sacc[bn][3];
        }
        rs0 += __shfl_xor_sync(0xffffffffu, rs0, 1);
        rs0 += __shfl_xor_sync(0xffffffffu, rs0, 2);
        rs1 += __shfl_xor_sync(0xffffffffu, rs1, 1);
        rs1 += __shfl_xor_sync(0xffffffffu, rs1, 2);
        l0 = l0 * sc0 + rs0;
        l1 = l1 * sc1 + rs1;
        m0 = mn0; m1 = mn1;
        #pragma unroll
        for (int bn = 0; bn < 8; ++bn) {
            oacc[bn][0] *= sc0; oacc[bn][1] *= sc0;
            oacc[bn][2] *= sc1; oacc[bn][3] *= sc1;
        }

        // O += Phi*Vhi + Phi*Vlo + Plo*Vhi
        {
            uint32_t vhB = sb + oVh + (uint32_t)(cur * 8192);
            uint32_t vlB = sb + oVl + (uint32_t)(cur * 8192);
            #pragma unroll
            for (int ks = 0; ks < 4; ++ks) {
                uint32_t ah[4], al[4];
                #pragma unroll
                for (int q = 0; q < 4; ++q) {
                    int tl = 2 * ks + (q >> 1);
                    int c0 = (q & 1) * 2;
                    split2(sacc[tl][c0], sacc[tl][c0 + 1], ah[q], al[q]);
                }
                uint32_t kbyte = (uint32_t)(ks * 32 + lkoff);
                #pragma unroll
                for (int bn4 = 0; bn4 < 4; ++bn4) {
                    uint32_t bH[4], bL[4];
                    uint32_t off = SW128((uint32_t)((bn4 * 16 + lrow) * 128) + kbyte);
                    ldm_x4(bH, vhB + off);
                    ldm_x4(bL, vlB + off);
                    uint32_t bHl[2] = {bH[0], bH[2]}, bHh[2] = {bH[1], bH[3]};
                    uint32_t bLl[2] = {bL[0], bL[2]}, bLh[2] = {bL[1], bL[3]};
                    mma_16816(oacc[2 * bn4],     ah, bHl);
                    mma_16816(oacc[2 * bn4 + 1], ah, bHh);
                    mma_16816(oacc[2 * bn4],     ah, bLl);
                    mma_16816(oacc[2 * bn4 + 1], ah, bLh);
                    mma_16816(oacc[2 * bn4],     al, bHl);
                    mma_16816(oacc[2 * bn4 + 1], al, bHh);
                }
            }
        }
    }

    float il0 = 1.f / l0, il1 = 1.f / l1;
    int row0 = q0 + wid * 16 + g2;
    size_t n0 = (size_t)b * Sv + row0;
    #pragma unroll
    for (int bn = 0; bn < 8; ++bn) {
        int col = h * 64 + bn * 8 + 2 * t4;
        #pragma unroll
        for (int half = 0; half < 2; ++half) {
            float v0 = oacc[bn][half * 2]     * (half ? il1 : il0);
            float v1 = oacc[bn][half * 2 + 1] * (half ? il1 : il0);
            uint32_t hp, lp;
            split2(v0, v1, hp, lp);
            size_t base = (n0 + half * 8) * Dv + col;
            *(uint32_t*)(g_ash + base) = hp;
            *(uint32_t*)(g_asl + base) = lp;
        }
    }
}

// ---------------------------------------------------------------------------
extern "C" void kernel_launch(void* const* d_in, const int* in_sizes, int n_in,
                              void* d_out, int out_size)
{
    const float* x  = (const float*)d_in[0];
    const int*   tp = (const int*)d_in[1];
    const float* w0 = (const float*)d_in[2];
    const float* w1 = (const float*)d_in[3];
    const float* w2 = (const float*)d_in[4];
    const float* w3 = (const float*)d_in[5];
    float* out = (float*)d_out;

    const int gemm_smem = 3 * 65536 + 1024;   // 193 KB, 3-stage super-slabs
    cudaFuncSetAttribute(gemm_qkv, cudaFuncAttributeMaxDynamicSharedMemorySize,
                         gemm_smem);
    cudaFuncSetAttribute(gemm_o, cudaFuncAttributeMaxDynamicSharedMemorySize,
                         gemm_smem);
    const int attn_smem = 64 * 1024 + 1024;   // KV double buffers only
    cudaFuncSetAttribute(attn_mma, cudaFuncAttributeMaxDynamicSharedMemorySize,
                         attn_smem);

    // 1) input/weight splits (hi/lo stored separately — no duplication)
    xsplit_kernel<<<(Nv * Dv) / (4 * 256), 256>>>(x);
    wsplit_kernel<<<4 * (Dv * Dv) / (4 * 256), 256>>>(w0, w1, w2, w3);

    // 2) fused QKV projection -> split bf16 attention operands directly
    gemm_qkv<<<dim3(24, Nv / 128), 256, gemm_smem>>>(tp);

    // 3) V transpose (bf16 -> bf16)
    v_prep2<<<dim3(Sv / 64, BHv), 256>>>();

    // 4) attention (writes hi/lo bf16 g_ash/g_asl directly)
    attn_mma<<<dim3(Sv / 128, Hv, Bv), 256, attn_smem>>>();

    // 5) output projection
    gemm_o<<<dim3(Dv / 128, Nv / 128), 256, gemm_smem>>>(out);
}

// round 12
// speedup vs baseline: 1.0277x; 1.0277x over previous
#include <cuda_runtime.h>
#include <cuda_bf16.h>
#include <math.h>
#include <stdint.h>

// Problem constants
#define Bv 2
#define Sv 2048
#define Dv 1024
#define Hv 16
#define DKv 64
#define Nv (Bv * Sv)     // 4096 rows
#define BHv (Bv * Hv)    // 32
#define NSLAB 48         // 3 terms x 16 K-chunks of 64

// ---------------------------------------------------------------------------
// Scratch (device globals — no cudaMalloc allowed). Hi/lo stored separately.
// ---------------------------------------------------------------------------
__device__ __nv_bfloat16 g_xh[(size_t)Nv * Dv];
__device__ __nv_bfloat16 g_xl[(size_t)Nv * Dv];
__device__ __nv_bfloat16 g_ash[(size_t)Nv * Dv];   // attention out hi
__device__ __nv_bfloat16 g_asl[(size_t)Nv * Dv];   // attention out lo
__device__ __nv_bfloat16 g_wh[4][(size_t)Dv * Dv];
__device__ __nv_bfloat16 g_wl[4][(size_t)Dv * Dv];
__device__ __nv_bfloat16 g_qh[(size_t)BHv * Sv * DKv];    // [bh][s][dk]
__device__ __nv_bfloat16 g_ql[(size_t)BHv * Sv * DKv];
__device__ __nv_bfloat16 g_kh[(size_t)BHv * Sv * DKv];
__device__ __nv_bfloat16 g_kl[(size_t)BHv * Sv * DKv];
__device__ __nv_bfloat16 g_vsh[(size_t)BHv * Sv * DKv];   // V split, s-major
__device__ __nv_bfloat16 g_vsl[(size_t)BHv * Sv * DKv];
__device__ __nv_bfloat16 g_vh[(size_t)BHv * DKv * Sv];    // [bh][dk][s]
__device__ __nv_bfloat16 g_vl[(size_t)BHv * DKv * Sv];

__device__ __forceinline__ uint32_t smem_to_u32(const void* p) {
    uint32_t a;
    asm("{ .reg .u64 t; cvta.to.shared.u64 t, %1; cvt.u32.u64 %0, t; }"
        : "=r"(a) : "l"(p));
    return a;
}
#define SW128(off) ((off) ^ (((off) >> 3) & 0x70))

__device__ __forceinline__ void ldm_x4(uint32_t* r, uint32_t addr) {
    asm volatile("ldmatrix.sync.aligned.m8n8.x4.shared.b16 {%0,%1,%2,%3}, [%4];"
        : "=r"(r[0]), "=r"(r[1]), "=r"(r[2]), "=r"(r[3]) : "r"(addr));
}
__device__ __forceinline__ void mma_16816(float* d, const uint32_t* a,
                                          const uint32_t* b) {
    asm volatile(
        "mma.sync.aligned.m16n8k16.row.col.f32.bf16.bf16.f32 "
        "{%0,%1,%2,%3}, {%4,%5,%6,%7}, {%8,%9}, {%0,%1,%2,%3};"
        : "+f"(d[0]), "+f"(d[1]), "+f"(d[2]), "+f"(d[3])
        : "r"(a[0]), "r"(a[1]), "r"(a[2]), "r"(a[3]), "r"(b[0]), "r"(b[1]));
}
__device__ __forceinline__ void cpa16(uint32_t dst, const void* src) {
    asm volatile("cp.async.cg.shared.global [%0], [%1], 16;"
        :: "r"(dst), "l"(src));
}
#define CP_COMMIT() asm volatile("cp.async.commit_group;" ::: "memory")
#define CP_WAIT(n)  asm volatile("cp.async.wait_group %0;" :: "n"(n) : "memory")

// split a float pair into hi/lo bf16x2 words
__device__ __forceinline__ void split2(float a, float b, uint32_t& h, uint32_t& l) {
    __nv_bfloat162 hp = __floats2bfloat162_rn(a, b);
    float r0 = __bfloat162float(hp.x), r1 = __bfloat162float(hp.y);
    __nv_bfloat162 lp = __floats2bfloat162_rn(a - r0, b - r1);
    h = *(uint32_t*)&hp;
    l = *(uint32_t*)&lp;
}

// ---------------------------------------------------------------------------
// Split fp32 -> separate hi/lo bf16 arrays (same [r][1024] layout)
// ---------------------------------------------------------------------------
__device__ __forceinline__ void split_body(
    const float* __restrict__ src, __nv_bfloat16* __restrict__ dh,
    __nv_bfloat16* __restrict__ dl, size_t e0)
{
    float4 v = *(const float4*)(src + e0);
    uint2 hu, lu;
    split2(v.x, v.y, hu.x, lu.x);
    split2(v.z, v.w, hu.y, lu.y);
    *(uint2*)(dh + e0) = hu;
    *(uint2*)(dl + e0) = lu;
}

__global__ __launch_bounds__(256) void xsplit_kernel(const float* __restrict__ x)
{
    size_t e0 = ((size_t)blockIdx.x * 256 + threadIdx.x) * 4;
    split_body(x, g_xh, g_xl, e0);
}

__global__ __launch_bounds__(256) void wsplit_kernel(
    const float* __restrict__ w0, const float* __restrict__ w1,
    const float* __restrict__ w2, const float* __restrict__ w3)
{
    int i = blockIdx.x >> 10;
    const float* src = (i == 0) ? w0 : (i == 1) ? w1 : (i == 2) ? w2 : w3;
    size_t e0 = ((size_t)(blockIdx.x & 1023) * 256 + threadIdx.x) * 4;
    split_body(src, g_wh[i], g_wl[i], e0);
}

// ---------------------------------------------------------------------------
// GEMM (R10 structure, proven): 128x128 CTA tile, 48 slabs of K=64.
// Slab s: term t = s>>4 selects (Ah,Bh) / (Ah,Bl) / (Al,Bh); chunk k = s&15.
// 3-stage cp.async (32KB stages, 96KB total -> 2 CTAs/SM), 1 sync per slab.
// mode: 0 = fp32 store; 1 = K RoPE split; 2 = Q RoPE+1/8 split; 3 = V split.
// ---------------------------------------------------------------------------
__device__ __forceinline__ void gemm_load_slab(
    const __nv_bfloat16* __restrict__ Ah, const __nv_bfloat16* __restrict__ Al,
    const __nv_bfloat16* __restrict__ Bh, const __nv_bfloat16* __restrict__ Bl,
    uint32_t bufu, int s, int tid)
{
    const int t = s >> 4;
    const int k = s & 15;
    const __nv_bfloat16* As = (t == 2) ? Al : Ah;
    const __nv_bfloat16* Bs = (t == 1) ? Bl : Bh;
    #pragma unroll
    for (int kk = 0; kk < 4; ++kk) {
        int idx = kk * 256 + tid;
        int r = idx >> 3, c = idx & 7;
        size_t goff = (size_t)r * Dv + k * 64 + c * 8;
        uint32_t so = SW128((uint32_t)(r * 128 + c * 16));
        cpa16(bufu + so,         As + goff);
        cpa16(bufu + 16384 + so, Bs + goff);
    }
}

__device__ __forceinline__ void gemm_tile(
    const __nv_bfloat16* __restrict__ Ah, const __nv_bfloat16* __restrict__ Al,
    const __nv_bfloat16* __restrict__ Bh, const __nv_bfloat16* __restrict__ Bl,
    const int* __restrict__ tp, int mode, int m0, int e0, uint32_t sbu,
    float* __restrict__ Y, __nv_bfloat16* __restrict__ dh,
    __nv_bfloat16* __restrict__ dl)
{
    const int tid = threadIdx.x;
    const int wid = tid >> 5;
    const int lane = tid & 31;
    const int wm = wid >> 1;
    const int wn = wid & 1;
    const int g2 = lane >> 2;
    const int t4 = lane & 3;
    const int lrow = lane & 15;
    const int lkoff = ((lane >> 4) & 1) * 16;

    float acc[2][8][4];
    #pragma unroll
    for (int i = 0; i < 2; ++i)
        #pragma unroll
        for (int j = 0; j < 8; ++j)
            #pragma unroll
            for (int k = 0; k < 4; ++k) acc[i][j][k] = 0.f;

    // prologue: slabs 0,1 -> stages 0,1
    gemm_load_slab(Ah, Al, Bh, Bl, sbu, 0, tid);
    CP_COMMIT();
    gemm_load_slab(Ah, Al, Bh, Bl, sbu + 32768, 1, tid);
    CP_COMMIT();

    int cc = 0;   // current stage = s % 3
    for (int s = 0; s < NSLAB; ++s) {
        if (s + 1 < NSLAB) { CP_WAIT(1); } else { CP_WAIT(0); }
        __syncthreads();
        if (s + 2 < NSLAB) {
            int nb = cc + 2; if (nb >= 3) nb -= 3;
            gemm_load_slab(Ah, Al, Bh, Bl, sbu + (uint32_t)(nb * 32768),
                           s + 2, tid);
            CP_COMMIT();
        }

        const uint32_t pAu = sbu + (uint32_t)(cc * 32768);
        const uint32_t pBu = pAu + 16384;
        #pragma unroll
        for (int ks = 0; ks < 4; ++ks) {
            const uint32_t kbyte = (uint32_t)(ks * 32 + lkoff);
            uint32_t afr[2][4], bfr[4][4];
            #pragma unroll
            for (int am = 0; am < 2; ++am) {
                uint32_t off = (uint32_t)((wm * 32 + am * 16 + lrow) * 128) + kbyte;
                ldm_x4(afr[am], pAu + SW128(off));
            }
            #pragma unroll
            for (int bn = 0; bn < 4; ++bn) {
                uint32_t off = (uint32_t)((wn * 64 + bn * 16 + lrow) * 128) + kbyte;
                ldm_x4(bfr[bn], pBu + SW128(off));
            }
            #pragma unroll
            for (int am = 0; am < 2; ++am)
                #pragma unroll
                for (int bn = 0; bn < 4; ++bn) {
                    uint32_t blo[2] = {bfr[bn][0], bfr[bn][2]};
                    uint32_t bhi[2] = {bfr[bn][1], bfr[bn][3]};
                    mma_16816(acc[am][bn * 2],     afr[am], blo);
                    mma_16816(acc[am][bn * 2 + 1], afr[am], bhi);
                }
        }
        ++cc; if (cc == 3) cc = 0;
    }

    const float qs = (mode == 2) ? 0.125f : 1.0f;
    const float LTH = 0.2878231366242557f;   // ln(10000)/32
    #pragma unroll
    for (int am = 0; am < 2; ++am) {
        #pragma unroll
        for (int half = 0; half < 2; ++half) {
            int m = m0 + wm * 32 + am * 16 + g2 + half * 8;
            int sr = m & (Sv - 1);
            float pos = (mode == 1 || mode == 2) ? (float)tp[sr] : 0.f;
            #pragma unroll
            for (int bn = 0; bn < 8; ++bn) {
                int e = e0 + wn * 64 + bn * 8 + t4 * 2;
                float d0 = acc[am][bn][half * 2];
                float d1 = acc[am][bn][half * 2 + 1];
                if (mode == 1 || mode == 2) {
                    int p = (e & (DKv - 1)) >> 1;
                    float inv = expf(-LTH * (float)p);
                    float sn, cs;
                    sincosf(pos * inv, &sn, &cs);
                    float o0 = (cs * d0 - sn * d1) * qs;
                    float o1 = (sn * d0 + cs * d1) * qs;
                    d0 = o0; d1 = o1;
                }
                if (mode == 0) {
                    *(float2*)(Y + (size_t)m * Dv + e) = make_float2(d0, d1);
                } else {
                    int bh = (m >> 11) * Hv + (e >> 6);
                    int dk = e & (DKv - 1);
                    size_t idx = ((size_t)bh * Sv + sr) * DKv + dk;
                    uint32_t h, l;
                    split2(d0, d1, h, l);
                    *(uint32_t*)(dh + idx) = h;
                    *(uint32_t*)(dl + idx) = l;
                }
            }
        }
    }
}

// Fused QKV projection: grid (24, 32); region = blockIdx.x >> 3 (0=Q,1=K,2=V)
__global__ __launch_bounds__(256, 2) void gemm_qkv(const int* __restrict__ tp)
{
    extern __shared__ char smraw[];
    uint32_t su = smem_to_u32(smraw);
    uint32_t sbu = (su + 1023u) & ~1023u;

    const int region = blockIdx.x >> 3;
    const int e0 = (blockIdx.x & 7) * 128;
    const int m0 = blockIdx.y * 128;
    const __nv_bfloat16* Ah = g_xh + (size_t)m0 * Dv;
    const __nv_bfloat16* Al = g_xl + (size_t)m0 * Dv;
    const __nv_bfloat16* Bh = g_wh[region] + (size_t)e0 * Dv;
    const __nv_bfloat16* Bl = g_wl[region] + (size_t)e0 * Dv;
    __nv_bfloat16* dh = (region == 0) ? g_qh : (region == 1) ? g_kh : g_vsh;
    __nv_bfloat16* dl = (region == 0) ? g_ql : (region == 1) ? g_kl : g_vsl;
    const int mode = (region == 0) ? 2 : (region == 1) ? 1 : 3;
    gemm_tile(Ah, Al, Bh, Bl, tp, mode, m0, e0, sbu, (float*)0, dh, dl);
}

// Output projection: grid (8, 32)
__global__ __launch_bounds__(256, 2) void gemm_o(float* __restrict__ out)
{
    extern __shared__ char smraw[];
    uint32_t su = smem_to_u32(smraw);
    uint32_t sbu = (su + 1023u) & ~1023u;

    const int e0 = blockIdx.x * 128;
    const int m0 = blockIdx.y * 128;
    gemm_tile(g_ash + (size_t)m0 * Dv, g_asl + (size_t)m0 * Dv,
              g_wh[3] + (size_t)e0 * Dv, g_wl[3] + (size_t)e0 * Dv,
              (const int*)0, 0, m0, e0, sbu, out,
              (__nv_bfloat16*)0, (__nv_bfloat16*)0);
}

// ---------------------------------------------------------------------------
// bf16 transpose: g_vsh/g_vsl [bh][s][64] -> g_vh/g_vl [bh][dk][s]
// ---------------------------------------------------------------------------
__global__ __launch_bounds__(256) void v_prep2()
{
    __shared__ __nv_bfloat16 sv[64][72];
    const int tid = threadIdx.x;
    const int st = blockIdx.x, bh = blockIdx.y;
    const int s0 = st * 64;

    #pragma unroll
    for (int pass = 0; pass < 2; ++pass) {
        const __nv_bfloat16* src = pass ? g_vsl : g_vsh;
        __nv_bfloat16* dst = pass ? g_vl : g_vh;
        if (pass) __syncthreads();
        #pragma unroll
        for (int p = 0; p < 2; ++p) {
            int idx = p * 256 + tid;         // 0..511 x 16B chunks
            int r = idx >> 3;
            int c = (idx & 7) * 8;
            *(uint4*)&sv[r][c] =
                *(const uint4*)(src + ((size_t)bh * Sv + s0 + r) * DKv + c);
        }
        __syncthreads();

        int dk = tid >> 2;
        int t0 = (tid & 3) * 16;
        uint32_t u[8];
        #pragma unroll
        for (int i = 0; i < 8; ++i) {
            __nv_bfloat162 p2 = {sv[t0 + 2*i][dk], sv[t0 + 2*i + 1][dk]};
            u[i] = *(uint32_t*)&p2;
        }
        size_t o = ((size_t)bh * DKv + dk) * Sv + s0 + t0;
        *(uint4*)(dst + o)     = make_uint4(u[0], u[1], u[2], u[3]);
        *(uint4*)(dst + o + 8) = make_uint4(u[4], u[5], u[6], u[7]);
    }
}

// ---------------------------------------------------------------------------
// Flash attention on mma.sync, 3-term split for QK^T and PV (proven R10 body)
// ---------------------------------------------------------------------------
__device__ __forceinline__ void attn_load_tile(
    uint32_t sb, int bh, int j, int buf, int tid)
{
    const uint32_t oKh = 0, oKl = 16384, oVh = 32768, oVl = 49152;
    const char* kh = (const char*)(g_kh + ((size_t)bh * Sv + j * 64) * 64);
    const char* kl = (const char*)(g_kl + ((size_t)bh * Sv + j * 64) * 64);
    #pragma unroll
    for (int p = 0; p < 2; ++p) {
        int idx = p * 256 + tid;
        int r = idx >> 3, c = idx & 7;
        uint32_t so = SW128((uint32_t)(r * 128 + c * 16));
        uint32_t bo = (uint32_t)(buf * 8192);
        cpa16(sb + oKh + bo + so, kh + idx * 16);
        cpa16(sb + oKl + bo + so, kl + idx * 16);
        const char* vh = (const char*)(g_vh + ((size_t)bh * 64 + r) * Sv + j * 64);
        const char* vl = (const char*)(g_vl + ((size_t)bh * 64 + r) * Sv + j * 64);
        cpa16(sb + oVh + bo + so, vh + c * 16);
        cpa16(sb + oVl + bo + so, vl + c * 16);
    }
}

__global__ __launch_bounds__(256, 1) void attn_mma()
{
    extern __shared__ char smraw[];
    uint32_t su = smem_to_u32(smraw);
    uint32_t sb = (su + 1023u) & ~1023u;
    const uint32_t oKh = 0, oKl = 16384, oVh = 32768, oVl = 49152;

    const int tid = threadIdx.x;
    const int wid = tid >> 5, lane = tid & 31;
    const int g2 = lane >> 2, t4 = lane & 3;
    const int lrow = lane & 15;
    const int lkoff = ((lane >> 4) & 1) * 16;

    const int qt = gridDim.x - 1 - blockIdx.x;   // big tiles first
    const int h = blockIdx.y, b = blockIdx.z;
    const int bh = b * Hv + h;
    const int q0 = qt * 128;
    const int jmax = 2 * qt + 1;

    // --- stage Q through smem (reusing K buffer space), hoist frags to regs
    uint32_t qfh[4][4], qfl[4][4];
    {
        const char* qh = (const char*)(g_qh + ((size_t)bh * Sv + q0) * 64);
        const char* ql = (const char*)(g_ql + ((size_t)bh * Sv + q0) * 64);
        #pragma unroll
        for (int p = 0; p < 4; ++p) {
            int idx = p * 256 + tid;
            uint32_t so = SW128((uint32_t)(idx * 16));
            cpa16(sb + so,         qh + idx * 16);
            cpa16(sb + 16384 + so, ql + idx * 16);
        }
        CP_COMMIT();
        CP_WAIT(0);
        __syncthreads();
        #pragma unroll
        for (int ks = 0; ks < 4; ++ks) {
            uint32_t aoff =
                SW128((uint32_t)((wid * 16 + lrow) * 128 + ks * 32 + lkoff));
            ldm_x4(qfh[ks], sb + aoff);
            ldm_x4(qfl[ks], sb + 16384 + aoff);
        }
        __syncthreads();
        attn_load_tile(sb, bh, 0, 0, tid);
        CP_COMMIT();
    }

    float m0 = -1e30f, m1 = -1e30f, l0 = 0.f, l1 = 0.f;
    float oacc[8][4];
    #pragma unroll
    for (int i = 0; i < 8; ++i)
        #pragma unroll
        for (int c = 0; c < 4; ++c) oacc[i][c] = 0.f;

    for (int j = 0; j <= jmax; ++j) {
        const int cur = j & 1;
        CP_WAIT(0);
        __syncthreads();
        if (j < jmax) {
            attn_load_tile(sb, bh, j + 1, cur ^ 1, tid);
            CP_COMMIT();
        }

        // S = Qhi*Khi + Qhi*Klo + Qlo*Khi (Q frags in regs)
        float sacc[8][4];
        #pragma unroll
        for (int i = 0; i < 8; ++i)
            #pragma unroll
            for (int c = 0; c < 4; ++c) sacc[i][c] = 0.f;
        {
            const uint32_t kb = (uint32_t)(cur * 8192);
            const uint32_t khB = sb + oKh + kb, klB = sb + oKl + kb;
            #pragma unroll
            for (int ks = 0; ks < 4; ++ks) {
                uint32_t kbyte = (uint32_t)(ks * 32 + lkoff);
                #pragma unroll
                for (int bn4 = 0; bn4 < 4; ++bn4) {
                    uint32_t boff = SW128((uint32_t)((bn4 * 16 + lrow) * 128) + kbyte);
                    uint32_t bh_[4], bl_[4];
                    ldm_x4(bh_, khB + boff);
                    ldm_x4(bl_, klB + boff);
                    uint32_t bhl[2] = {bh_[0], bh_[2]}, bhh[2] = {bh_[1], bh_[3]};
                    uint32_t bll[2] = {bl_[0], bl_[2]}, blh[2] = {bl_[1], bl_[3]};
                    mma_16816(sacc[2 * bn4],     qfh[ks], bhl);
                    mma_16816(sacc[2 * bn4 + 1], qfh[ks], bhh);
                    mma_16816(sacc[2 * bn4],     qfh[ks], bll);
                    mma_16816(sacc[2 * bn4 + 1], qfh[ks], blh);
                    mma_16816(sacc[2 * bn4],     qfl[ks], bhl);
                    mma_16816(sacc[2 * bn4 + 1], qfl[ks], bhh);
                }
            }
        }

        if (j >= 2 * qt) {
            int r0 = q0 + wid * 16 + g2;
            #pragma unroll
            for (int bn = 0; bn < 8; ++bn) {
                int col = j * 64 + bn * 8 + 2 * t4;
                #pragma unroll
                for (int c = 0; c < 4; ++c) {
                    int row = r0 + ((c >= 2) ? 8 : 0);
                    if (col + (c & 1) > row) sacc[bn][c] = -1e30f;
                }
            }
        }

        float tm0 = -1e30f, tm1 = -1e30f;
        #pragma unroll
        for (int bn = 0; bn < 8; ++bn) {
            tm0 = fmaxf(tm0, fmaxf(sacc[bn][0], sacc[bn][1]));
            tm1 = fmaxf(tm1, fmaxf(sacc[bn][2], sacc[bn][3]));
        }
        tm0 = fmaxf(tm0, __shfl_xor_sync(0xffffffffu, tm0, 1));
        tm0 = fmaxf(tm0, __shfl_xor_sync(0xffffffffu, tm0, 2));
        tm1 = fmaxf(tm1, __shfl_xor_sync(0xffffffffu, tm1, 1));
        tm1 = fmaxf(tm1, __shfl_xor_sync(0xffffffffu, tm1, 2));
        float mn0 = fmaxf(m0, tm0), mn1 = fmaxf(m1, tm1);
        float sc0 = __expf(m0 - mn0), sc1 = __expf(m1 - mn1);
        float rs0 = 0.f, rs1 = 0.f;
        #pragma unroll
        for (int bn = 0; bn < 8; ++bn) {
            sacc[bn][0] = __expf(sacc[bn][0] - mn0);
            sacc[bn][1] = __expf(sacc[bn][1] - mn0);
            sacc[bn][2] = __expf(sacc[bn][2] - mn1);
            sacc[bn][3] = __expf(sacc[bn][3] - mn1);
            rs0 += sacc[bn][0] + sacc[bn][1];
            rs1 += sacc[bn][2] + sacc[bn][3];
        }
        rs0 += __shfl_xor_sync(0xffffffffu, rs0, 1);
        rs0 += __shfl_xor_sync(0xffffffffu, rs0, 2);
        rs1 += __shfl_xor_sync(0xffffffffu, rs1, 1);
        rs1 += __shfl_xor_sync(0xffffffffu, rs1, 2);
        l0 = l0 * sc0 + rs0;
        l1 = l1 * sc1 + rs1;
        m0 = mn0; m1 = mn1;
        #pragma unroll
        for (int bn = 0; bn < 8; ++bn) {
            oacc[bn][0] *= sc0; oacc[bn][1] *= sc0;
            oacc[bn][2] *= sc1; oacc[bn][3] *= sc1;
        }

        // O += Phi*Vhi + Phi*Vlo + Plo*Vhi
        {
            uint32_t vhB = sb + oVh + (uint32_t)(cur * 8192);
            uint32_t vlB = sb + oVl + (uint32_t)(cur * 8192);
            #pragma unroll
            for (int ks = 0; ks < 4; ++ks) {
                uint32_t ah[4], al[4];
                #pragma unroll
                for (int q = 0; q < 4; ++q) {
                    int tl = 2 * ks + (q >> 1);
                    int c0 = (q & 1) * 2;
                    split2(sacc[tl][c0], sacc[tl][c0 + 1], ah[q], al[q]);
                }
                uint32_t kbyte = (uint32_t)(ks * 32 + lkoff);
                #pragma unroll
                for (int bn4 = 0; bn4 < 4; ++bn4) {
                    uint32_t bH[4], bL[4];
                    uint32_t off = SW128((uint32_t)((bn4 * 16 + lrow) * 128) + kbyte);
                    ldm_x4(bH, vhB + off);
                    ldm_x4(bL, vlB + off);
                    uint32_t bHl[2] = {bH[0], bH[2]}, bHh[2] = {bH[1], bH[3]};
                    uint32_t bLl[2] = {bL[0], bL[2]}, bLh[2] = {bL[1], bL[3]};
                    mma_16816(oacc[2 * bn4],     ah, bHl);
                    mma_16816(oacc[2 * bn4 + 1], ah, bHh);
                    mma_16816(oacc[2 * bn4],     ah, bLl);
                    mma_16816(oacc[2 * bn4 + 1], ah, bLh);
                    mma_16816(oacc[2 * bn4],     al, bHl);
                    mma_16816(oacc[2 * bn4 + 1], al, bHh);
                }
            }
        }
    }

    float il0 = 1.f / l0, il1 = 1.f / l1;
    int row0 = q0 + wid * 16 + g2;
    size_t n0 = (size_t)b * Sv + row0;
    #pragma unroll
    for (int bn = 0; bn < 8; ++bn) {
        int col = h * 64 + bn * 8 + 2 * t4;
        #pragma unroll
        for (int half = 0; half < 2; ++half) {
            float v0 = oacc[bn][half * 2]     * (half ? il1 : il0);
            float v1 = oacc[bn][half * 2 + 1] * (half ? il1 : il0);
            uint32_t hp, lp;
            split2(v0, v1, hp, lp);
            size_t base = (n0 + half * 8) * Dv + col;
            *(uint32_t*)(g_ash + base) = hp;
            *(uint32_t*)(g_asl + base) = lp;
        }
    }
}

// ---------------------------------------------------------------------------
extern "C" void kernel_launch(void* const* d_in, const int* in_sizes, int n_in,
                              void* d_out, int out_size)
{
    const float* x  = (const float*)d_in[0];
    const int*   tp = (const int*)d_in[1];
    const float* w0 = (const float*)d_in[2];
    const float* w1 = (const float*)d_in[3];
    const float* w2 = (const float*)d_in[4];
    const float* w3 = (const float*)d_in[5];
    float* out = (float*)d_out;

    const int gemm_smem = 3 * 32768 + 1024;   // 97 KB -> 2 CTAs/SM
    cudaFuncSetAttribute(gemm_qkv, cudaFuncAttributeMaxDynamicSharedMemorySize,
                         gemm_smem);
    cudaFuncSetAttribute(gemm_o, cudaFuncAttributeMaxDynamicSharedMemorySize,
                         gemm_smem);
    const int attn_smem = 64 * 1024 + 1024;   // KV double buffers only
    cudaFuncSetAttribute(attn_mma, cudaFuncAttributeMaxDynamicSharedMemorySize,
                         attn_smem);

    // 1) input/weight splits (hi/lo stored separately)
    xsplit_kernel<<<(Nv * Dv) / (4 * 256), 256>>>(x);
    wsplit_kernel<<<4 * (Dv * Dv) / (4 * 256), 256>>>(w0, w1, w2, w3);

    // 2) fused QKV projection -> split bf16 attention operands directly
    gemm_qkv<<<dim3(24, Nv / 128), 256, gemm_smem>>>(tp);

    // 3) V transpose (bf16 -> bf16)
    v_prep2<<<dim3(Sv / 64, BHv), 256>>>();

    // 4) attention (writes hi/lo bf16 g_ash/g_asl directly)
    attn_mma<<<dim3(Sv / 128, Hv, Bv), 256, attn_smem>>>();

    // 5) output projection
    gemm_o<<<dim3(Dv / 128, Nv / 128), 256, gemm_smem>>>(out);
}

// round 13
// speedup vs baseline: 1.0338x; 1.0060x over previous
#include <cuda_runtime.h>
#include <cuda_bf16.h>
#include <math.h>
#include <stdint.h>

// Problem constants
#define Bv 2
#define Sv 2048
#define Dv 1024
#define Hv 16
#define DKv 64
#define Nv (Bv * Sv)     // 4096 rows
#define BHv (Bv * Hv)    // 32
#define NSLAB 48         // 3 terms x 16 K-chunks of 64

// ---------------------------------------------------------------------------
// Scratch (device globals — no cudaMalloc allowed). Hi/lo stored separately.
// ---------------------------------------------------------------------------
__device__ __nv_bfloat16 g_xh[(size_t)Nv * Dv];
__device__ __nv_bfloat16 g_xl[(size_t)Nv * Dv];
__device__ __nv_bfloat16 g_ash[(size_t)Nv * Dv];   // attention out hi
__device__ __nv_bfloat16 g_asl[(size_t)Nv * Dv];   // attention out lo
__device__ __nv_bfloat16 g_wh[4][(size_t)Dv * Dv];
__device__ __nv_bfloat16 g_wl[4][(size_t)Dv * Dv];
__device__ __nv_bfloat16 g_qh[(size_t)BHv * Sv * DKv];    // [bh][s][dk]
__device__ __nv_bfloat16 g_ql[(size_t)BHv * Sv * DKv];
__device__ __nv_bfloat16 g_kh[(size_t)BHv * Sv * DKv];
__device__ __nv_bfloat16 g_kl[(size_t)BHv * Sv * DKv];
__device__ __nv_bfloat16 g_vh[(size_t)BHv * DKv * Sv];    // [bh][dk][s]
__device__ __nv_bfloat16 g_vl[(size_t)BHv * DKv * Sv];

__device__ __forceinline__ uint32_t smem_to_u32(const void* p) {
    uint32_t a;
    asm("{ .reg .u64 t; cvta.to.shared.u64 t, %1; cvt.u32.u64 %0, t; }"
        : "=r"(a) : "l"(p));
    return a;
}
#define SW128(off) ((off) ^ (((off) >> 3) & 0x70))

__device__ __forceinline__ void ldm_x4(uint32_t* r, uint32_t addr) {
    asm volatile("ldmatrix.sync.aligned.m8n8.x4.shared.b16 {%0,%1,%2,%3}, [%4];"
        : "=r"(r[0]), "=r"(r[1]), "=r"(r[2]), "=r"(r[3]) : "r"(addr));
}
__device__ __forceinline__ void mma_16816(float* d, const uint32_t* a,
                                          const uint32_t* b) {
    asm volatile(
        "mma.sync.aligned.m16n8k16.row.col.f32.bf16.bf16.f32 "
        "{%0,%1,%2,%3}, {%4,%5,%6,%7}, {%8,%9}, {%0,%1,%2,%3};"
        : "+f"(d[0]), "+f"(d[1]), "+f"(d[2]), "+f"(d[3])
        : "r"(a[0]), "r"(a[1]), "r"(a[2]), "r"(a[3]), "r"(b[0]), "r"(b[1]));
}
__device__ __forceinline__ void cpa16(uint32_t dst, const void* src) {
    asm volatile("cp.async.cg.shared.global [%0], [%1], 16;"
        :: "r"(dst), "l"(src));
}
#define CP_COMMIT() asm volatile("cp.async.commit_group;" ::: "memory")
#define CP_WAIT(n)  asm volatile("cp.async.wait_group %0;" :: "n"(n) : "memory")

// split a float pair into hi/lo bf16x2 words
__device__ __forceinline__ void split2(float a, float b, uint32_t& h, uint32_t& l) {
    __nv_bfloat162 hp = __floats2bfloat162_rn(a, b);
    float r0 = __bfloat162float(hp.x), r1 = __bfloat162float(hp.y);
    __nv_bfloat162 lp = __floats2bfloat162_rn(a - r0, b - r1);
    h = *(uint32_t*)&hp;
    l = *(uint32_t*)&lp;
}

// ---------------------------------------------------------------------------
// Split fp32 -> separate hi/lo bf16 arrays (same [r][1024] layout)
// ---------------------------------------------------------------------------
__device__ __forceinline__ void split_body(
    const float* __restrict__ src, __nv_bfloat16* __restrict__ dh,
    __nv_bfloat16* __restrict__ dl, size_t e0)
{
    float4 v = *(const float4*)(src + e0);
    uint2 hu, lu;
    split2(v.x, v.y, hu.x, lu.x);
    split2(v.z, v.w, hu.y, lu.y);
    *(uint2*)(dh + e0) = hu;
    *(uint2*)(dl + e0) = lu;
}

__global__ __launch_bounds__(256) void xsplit_kernel(const float* __restrict__ x)
{
    size_t e0 = ((size_t)blockIdx.x * 256 + threadIdx.x) * 4;
    split_body(x, g_xh, g_xl, e0);
}

__global__ __launch_bounds__(256) void wsplit_kernel(
    const float* __restrict__ w0, const float* __restrict__ w1,
    const float* __restrict__ w2, const float* __restrict__ w3)
{
    int i = blockIdx.x >> 10;
    const float* src = (i == 0) ? w0 : (i == 1) ? w1 : (i == 2) ? w2 : w3;
    size_t e0 = ((size_t)(blockIdx.x & 1023) * 256 + threadIdx.x) * 4;
    split_body(src, g_wh[i], g_wl[i], e0);
}

// ---------------------------------------------------------------------------
// GEMM: 128x128 CTA tile, 48 slabs of K=64.
// Slab s: term t = s>>4 selects (Ah,Bh) / (Ah,Bl) / (Al,Bh); chunk k = s&15.
// 3-stage cp.async (32KB stages, 96KB -> 2 CTAs/SM), 1 sync per slab.
// mode: 0 = fp32 store; 1 = K RoPE split; 2 = Q RoPE+1/8 split;
//       3 = V split written TRANSPOSED [bh][dk][s] (fuses old v_prep2).
// ---------------------------------------------------------------------------
__device__ __forceinline__ void gemm_load_slab(
    const __nv_bfloat16* __restrict__ Ah, const __nv_bfloat16* __restrict__ Al,
    const __nv_bfloat16* __restrict__ Bh, const __nv_bfloat16* __restrict__ Bl,
    uint32_t bufu, int s, int tid)
{
    const int t = s >> 4;
    const int k = s & 15;
    const __nv_bfloat16* As = (t == 2) ? Al : Ah;
    const __nv_bfloat16* Bs = (t == 1) ? Bl : Bh;
    #pragma unroll
    for (int kk = 0; kk < 4; ++kk) {
        int idx = kk * 256 + tid;
        int r = idx >> 3, c = idx & 7;
        size_t goff = (size_t)r * Dv + k * 64 + c * 8;
        uint32_t so = SW128((uint32_t)(r * 128 + c * 16));
        cpa16(bufu + so,         As + goff);
        cpa16(bufu + 16384 + so, Bs + goff);
    }
}

__device__ __forceinline__ void gemm_tile(
    const __nv_bfloat16* __restrict__ Ah, const __nv_bfloat16* __restrict__ Al,
    const __nv_bfloat16* __restrict__ Bh, const __nv_bfloat16* __restrict__ Bl,
    const int* __restrict__ tp, int mode, int m0, int e0, uint32_t sbu,
    float* __restrict__ Y, __nv_bfloat16* __restrict__ dh,
    __nv_bfloat16* __restrict__ dl)
{
    const int tid = threadIdx.x;
    const int wid = tid >> 5;
    const int lane = tid & 31;
    const int wm = wid >> 1;
    const int wn = wid & 1;
    const int g2 = lane >> 2;
    const int t4 = lane & 3;
    const int lrow = lane & 15;
    const int lkoff = ((lane >> 4) & 1) * 16;

    float acc[2][8][4];
    #pragma unroll
    for (int i = 0; i < 2; ++i)
        #pragma unroll
        for (int j = 0; j < 8; ++j)
            #pragma unroll
            for (int k = 0; k < 4; ++k) acc[i][j][k] = 0.f;

    // prologue: slabs 0,1 -> stages 0,1
    gemm_load_slab(Ah, Al, Bh, Bl, sbu, 0, tid);
    CP_COMMIT();
    gemm_load_slab(Ah, Al, Bh, Bl, sbu + 32768, 1, tid);
    CP_COMMIT();

    int cc = 0;   // current stage = s % 3
    for (int s = 0; s < NSLAB; ++s) {
        if (s + 1 < NSLAB) { CP_WAIT(1); } else { CP_WAIT(0); }
        __syncthreads();
        if (s + 2 < NSLAB) {
            int nb = cc + 2; if (nb >= 3) nb -= 3;
            gemm_load_slab(Ah, Al, Bh, Bl, sbu + (uint32_t)(nb * 32768),
                           s + 2, tid);
            CP_COMMIT();
        }

        const uint32_t pAu = sbu + (uint32_t)(cc * 32768);
        const uint32_t pBu = pAu + 16384;
        #pragma unroll
        for (int ks = 0; ks < 4; ++ks) {
            const uint32_t kbyte = (uint32_t)(ks * 32 + lkoff);
            uint32_t afr[2][4], bfr[4][4];
            #pragma unroll
            for (int am = 0; am < 2; ++am) {
                uint32_t off = (uint32_t)((wm * 32 + am * 16 + lrow) * 128) + kbyte;
                ldm_x4(afr[am], pAu + SW128(off));
            }
            #pragma unroll
            for (int bn = 0; bn < 4; ++bn) {
                uint32_t off = (uint32_t)((wn * 64 + bn * 16 + lrow) * 128) + kbyte;
                ldm_x4(bfr[bn], pBu + SW128(off));
            }
            #pragma unroll
            for (int am = 0; am < 2; ++am)
                #pragma unroll
                for (int bn = 0; bn < 4; ++bn) {
                    uint32_t blo[2] = {bfr[bn][0], bfr[bn][2]};
                    uint32_t bhi[2] = {bfr[bn][1], bfr[bn][3]};
                    mma_16816(acc[am][bn * 2],     afr[am], blo);
                    mma_16816(acc[am][bn * 2 + 1], afr[am], bhi);
                }
        }
        ++cc; if (cc == 3) cc = 0;
    }

    const float qs = (mode == 2) ? 0.125f : 1.0f;
    const float LTH = 0.2878231366242557f;   // ln(10000)/32
    #pragma unroll
    for (int am = 0; am < 2; ++am) {
        #pragma unroll
        for (int half = 0; half < 2; ++half) {
            int m = m0 + wm * 32 + am * 16 + g2 + half * 8;
            int sr = m & (Sv - 1);
            float pos = (mode == 1 || mode == 2) ? (float)tp[sr] : 0.f;
            #pragma unroll
            for (int bn = 0; bn < 8; ++bn) {
                int e = e0 + wn * 64 + bn * 8 + t4 * 2;
                float d0 = acc[am][bn][half * 2];
                float d1 = acc[am][bn][half * 2 + 1];
                if (mode == 1 || mode == 2) {
                    int p = (e & (DKv - 1)) >> 1;
                    float inv = expf(-LTH * (float)p);
                    float sn, cs;
                    sincosf(pos * inv, &sn, &cs);
                    float o0 = (cs * d0 - sn * d1) * qs;
                    float o1 = (sn * d0 + cs * d1) * qs;
                    d0 = o0; d1 = o1;
                }
                if (mode == 0) {
                    *(float2*)(Y + (size_t)m * Dv + e) = make_float2(d0, d1);
                } else if (mode == 3) {
                    // V: write hi/lo transposed [bh][dk][s] directly
                    int bh = (m >> 11) * Hv + (e >> 6);
                    int dk = e & (DKv - 1);
                    size_t idx = ((size_t)bh * DKv + dk) * Sv + sr;
                    uint32_t h, l;
                    split2(d0, d1, h, l);
                    *(uint16_t*)((uint16_t*)g_vh + idx)      = (uint16_t)h;
                    *(uint16_t*)((uint16_t*)g_vh + idx + Sv) = (uint16_t)(h >> 16);
                    *(uint16_t*)((uint16_t*)g_vl + idx)      = (uint16_t)l;
                    *(uint16_t*)((uint16_t*)g_vl + idx + Sv) = (uint16_t)(l >> 16);
                } else {
                    int bh = (m >> 11) * Hv + (e >> 6);
                    int dk = e & (DKv - 1);
                    size_t idx = ((size_t)bh * Sv + sr) * DKv + dk;
                    uint32_t h, l;
                    split2(d0, d1, h, l);
                    *(uint32_t*)(dh + idx) = h;
                    *(uint32_t*)(dl + idx) = l;
                }
            }
        }
    }
}

// Fused QKV projection: grid (24, 32); region = blockIdx.x >> 3 (0=Q,1=K,2=V)
__global__ __launch_bounds__(256, 2) void gemm_qkv(const int* __restrict__ tp)
{
    extern __shared__ char smraw[];
    uint32_t su = smem_to_u32(smraw);
    uint32_t sbu = (su + 1023u) & ~1023u;

    const int region = blockIdx.x >> 3;
    const int e0 = (blockIdx.x & 7) * 128;
    const int m0 = blockIdx.y * 128;
    const __nv_bfloat16* Ah = g_xh + (size_t)m0 * Dv;
    const __nv_bfloat16* Al = g_xl + (size_t)m0 * Dv;
    const __nv_bfloat16* Bh = g_wh[region] + (size_t)e0 * Dv;
    const __nv_bfloat16* Bl = g_wl[region] + (size_t)e0 * Dv;
    __nv_bfloat16* dh = (region == 0) ? g_qh : g_kh;
    __nv_bfloat16* dl = (region == 0) ? g_ql : g_kl;
    const int mode = (region == 0) ? 2 : (region == 1) ? 1 : 3;
    gemm_tile(Ah, Al, Bh, Bl, tp, mode, m0, e0, sbu, (float*)0, dh, dl);
}

// Output projection: grid (8, 32)
__global__ __launch_bounds__(256, 2) void gemm_o(float* __restrict__ out)
{
    extern __shared__ char smraw[];
    uint32_t su = smem_to_u32(smraw);
    uint32_t sbu = (su + 1023u) & ~1023u;

    const int e0 = blockIdx.x * 128;
    const int m0 = blockIdx.y * 128;
    gemm_tile(g_ash + (size_t)m0 * Dv, g_asl + (size_t)m0 * Dv,
              g_wh[3] + (size_t)e0 * Dv, g_wl[3] + (size_t)e0 * Dv,
              (const int*)0, 0, m0, e0, sbu, out,
              (__nv_bfloat16*)0, (__nv_bfloat16*)0);
}

// ---------------------------------------------------------------------------
// Flash attention on mma.sync, 3-term split for QK^T and PV (proven R10 body)
// ---------------------------------------------------------------------------
__device__ __forceinline__ void attn_load_tile(
    uint32_t sb, int bh, int j, int buf, int tid)
{
    const uint32_t oKh = 0, oKl = 16384, oVh = 32768, oVl = 49152;
    const char* kh = (const char*)(g_kh + ((size_t)bh * Sv + j * 64) * 64);
    const char* kl = (const char*)(g_kl + ((size_t)bh * Sv + j * 64) * 64);
    #pragma unroll
    for (int p = 0; p < 2; ++p) {
        int idx = p * 256 + tid;
        int r = idx >> 3, c = idx & 7;
        uint32_t so = SW128((uint32_t)(r * 128 + c * 16));
        uint32_t bo = (uint32_t)(buf * 8192);
        cpa16(sb + oKh + bo + so, kh + idx * 16);
        cpa16(sb + oKl + bo + so, kl + idx * 16);
        const char* vh = (const char*)(g_vh + ((size_t)bh * 64 + r) * Sv + j * 64);
        const char* vl = (const char*)(g_vl + ((size_t)bh * 64 + r) * Sv + j * 64);
        cpa16(sb + oVh + bo + so, vh + c * 16);
        cpa16(sb + oVl + bo + so, vl + c * 16);
    }
}

__global__ __launch_bounds__(256, 1) void attn_mma()
{
    extern __shared__ char smraw[];
    uint32_t su = smem_to_u32(smraw);
    uint32_t sb = (su + 1023u) & ~1023u;
    const uint32_t oKh = 0, oKl = 16384, oVh = 32768, oVl = 49152;

    const int tid = threadIdx.x;
    const int wid = tid >> 5, lane = tid & 31;
    const int g2 = lane >> 2, t4 = lane & 3;
    const int lrow = lane & 15;
    const int lkoff = ((lane >> 4) & 1) * 16;

    const int qt = gridDim.x - 1 - blockIdx.x;   // big tiles first
    const int h = blockIdx.y, b = blockIdx.z;
    const int bh = b * Hv + h;
    const int q0 = qt * 128;
    const int jmax = 2 * qt + 1;

    // --- stage Q through smem (reusing K buffer space), hoist frags to regs
    uint32_t qfh[4][4], qfl[4][4];
    {
        const char* qh = (const char*)(g_qh + ((size_t)bh * Sv + q0) * 64);
        const char* ql = (const char*)(g_ql + ((size_t)bh * Sv + q0) * 64);
        #pragma unroll
        for (int p = 0; p < 4; ++p) {
            int idx = p * 256 + tid;
            uint32_t so = SW128((uint32_t)(idx * 16));
            cpa16(sb + so,         qh + idx * 16);
            cpa16(sb + 16384 + so, ql + idx * 16);
        }
        CP_COMMIT();
        CP_WAIT(0);
        __syncthreads();
        #pragma unroll
        for (int ks = 0; ks < 4; ++ks) {
            uint32_t aoff =
                SW128((uint32_t)((wid * 16 + lrow) * 128 + ks * 32 + lkoff));
            ldm_x4(qfh[ks], sb + aoff);
            ldm_x4(qfl[ks], sb + 16384 + aoff);
        }
        __syncthreads();
        attn_load_tile(sb, bh, 0, 0, tid);
        CP_COMMIT();
    }

    float m0 = -1e30f, m1 = -1e30f, l0 = 0.f, l1 = 0.f;
    float oacc[8][4];
    #pragma unroll
    for (int i = 0; i < 8; ++i)
        #pragma unroll
        for (int c = 0; c < 4; ++c) oacc[i][c] = 0.f;

    for (int j = 0; j <= jmax; ++j) {
        const int cur = j & 1;
        CP_WAIT(0);
        __syncthreads();
        if (j < jmax) {
            attn_load_tile(sb, bh, j + 1, cur ^ 1, tid);
            CP_COMMIT();
        }

        // S = Qhi*Khi + Qhi*Klo + Qlo*Khi (Q frags in regs)
        float sacc[8][4];
        #pragma unroll
        for (int i = 0; i < 8; ++i)
            #pragma unroll
            for (int c = 0; c < 4; ++c) sacc[i][c] = 0.f;
        {
            const uint32_t kb = (uint32_t)(cur * 8192);
            const uint32_t khB = sb + oKh + kb, klB = sb + oKl + kb;
            #pragma unroll
            for (int ks = 0; ks < 4; ++ks) {
                uint32_t kbyte = (uint32_t)(ks * 32 + lkoff);
                #pragma unroll
                for (int bn4 = 0; bn4 < 4; ++bn4) {
                    uint32_t boff = SW128((uint32_t)((bn4 * 16 + lrow) * 128) + kbyte);
                    uint32_t bh_[4], bl_[4];
                    ldm_x4(bh_, khB + boff);
                    ldm_x4(bl_, klB + boff);
                    uint32_t bhl[2] = {bh_[0], bh_[2]}, bhh[2] = {bh_[1], bh_[3]};
                    uint32_t bll[2] = {bl_[0], bl_[2]}, blh[2] = {bl_[1], bl_[3]};
                    mma_16816(sacc[2 * bn4],     qfh[ks], bhl);
                    mma_16816(sacc[2 * bn4 + 1], qfh[ks], bhh);
                    mma_16816(sacc[2 * bn4],     qfh[ks], bll);
                    mma_16816(sacc[2 * bn4 + 1], qfh[ks], blh);
                    mma_16816(sacc[2 * bn4],     qfl[ks], bhl);
                    mma_16816(sacc[2 * bn4 + 1], qfl[ks], bhh);
                }
            }
        }

        if (j >= 2 * qt) {
            int r0 = q0 + wid * 16 + g2;
            #pragma unroll
            for (int bn = 0; bn < 8; ++bn) {
                int col = j * 64 + bn * 8 + 2 * t4;
                #pragma unroll
                for (int c = 0; c < 4; ++c) {
                    int row = r0 + ((c >= 2) ? 8 : 0);
                    if (col + (c & 1) > row) sacc[bn][c] = -1e30f;
                }
            }
        }

        float tm0 = -1e30f, tm1 = -1e30f;
        #pragma unroll
        for (int bn = 0; bn < 8; ++bn) {
            tm0 = fmaxf(tm0, fmaxf(sacc[bn][0], sacc[bn][1]));
            tm1 = fmaxf(tm1, fmaxf(sacc[bn][2], sacc[bn][3]));
        }
        tm0 = fmaxf(tm0, __shfl_xor_sync(0xffffffffu, tm0, 1));
        tm0 = fmaxf(tm0, __shfl_xor_sync(0xffffffffu, tm0, 2));
        tm1 = fmaxf(tm1, __shfl_xor_sync(0xffffffffu, tm1, 1));
        tm1 = fmaxf(tm1, __shfl_xor_sync(0xffffffffu, tm1, 2));
        float mn0 = fmaxf(m0, tm0), mn1 = fmaxf(m1, tm1);
        float sc0 = __expf(m0 - mn0), sc1 = __expf(m1 - mn1);
        float rs0 = 0.f, rs1 = 0.f;
        #pragma unroll
        for (int bn = 0; bn < 8; ++bn) {
            sacc[bn][0] = __expf(sacc[bn][0] - mn0);
            sacc[bn][1] = __expf(sacc[bn][1] - mn0);
            sacc[bn][2] = __expf(sacc[bn][2] - mn1);
            sacc[bn][3] = __expf(sacc[bn][3] - mn1);
            rs0 += sacc[bn][0] + sacc[bn][1];
            rs1 += sacc[bn][2] + sacc[bn][3];
        }
        rs0 += __shfl_xor_sync(0xffffffffu, rs0, 1);
        rs0 += __shfl_xor_sync(0xffffffffu, rs0, 2);
        rs1 += __shfl_xor_sync(0xffffffffu, rs1, 1);
        rs1 += __shfl_xor_sync(0xffffffffu, rs1, 2);
        l0 = l0 * sc0 + rs0;
        l1 = l1 * sc1 + rs1;
        m0 = mn0; m1 = mn1;
        #pragma unroll
        for (int bn = 0; bn < 8; ++bn) {
            oacc[bn][0] *= sc0; oacc[bn][1] *= sc0;
            oacc[bn][2] *= sc1; oacc[bn][3] *= sc1;
        }

        // O += Phi*Vhi + Phi*Vlo + Plo*Vhi
        {
            uint32_t vhB = sb + oVh + (uint32_t)(cur * 8192);
            uint32_t vlB = sb + oVl + (uint32_t)(cur * 8192);
            #pragma unroll
            for (int ks = 0; ks < 4; ++ks) {
                uint32_t ah[4], al[4];
                #pragma unroll
                for (int q = 0; q < 4; ++q) {
                    int tl = 2 * ks + (q >> 1);
                    int c0 = (q & 1) * 2;
                    split2(sacc[tl][c0], sacc[tl][c0 + 1], ah[q], al[q]);
                }
                uint32_t kbyte = (uint32_t)(ks * 32 + lkoff);
                #pragma unroll
                for (int bn4 = 0; bn4 < 4; ++bn4) {
                    uint32_t bH[4], bL[4];
                    uint32_t off = SW128((uint32_t)((bn4 * 16 + lrow) * 128) + kbyte);
                    ldm_x4(bH, vhB + off);
                    ldm_x4(bL, vlB + off);
                    uint32_t bHl[2] = {bH[0], bH[2]}, bHh[2] = {bH[1], bH[3]};
                    uint32_t bLl[2] = {bL[0], bL[2]}, bLh[2] = {bL[1], bL[3]};
                    mma_16816(oacc[2 * bn4],     ah, bHl);
                    mma_16816(oacc[2 * bn4 + 1], ah, bHh);
                    mma_16816(oacc[2 * bn4],     ah, bLl);
                    mma_16816(oacc[2 * bn4 + 1], ah, bLh);
                    mma_16816(oacc[2 * bn4],     al, bHl);
                    mma_16816(oacc[2 * bn4 + 1], al, bHh);
                }
            }
        }
    }

    float il0 = 1.f / l0, il1 = 1.f / l1;
    int row0 = q0 + wid * 16 + g2;
    size_t n0 = (size_t)b * Sv + row0;
    #pragma unroll
    for (int bn = 0; bn < 8; ++bn) {
        int col = h * 64 + bn * 8 + 2 * t4;
        #pragma unroll
        for (int half = 0; half < 2; ++half) {
            float v0 = oacc[bn][half * 2]     * (half ? il1 : il0);
            float v1 = oacc[bn][half * 2 + 1] * (half ? il1 : il0);
            uint32_t hp, lp;
            split2(v0, v1, hp, lp);
            size_t base = (n0 + half * 8) * Dv + col;
            *(uint32_t*)(g_ash + base) = hp;
            *(uint32_t*)(g_asl + base) = lp;
        }
    }
}

// ---------------------------------------------------------------------------
extern "C" void kernel_launch(void* const* d_in, const int* in_sizes, int n_in,
                              void* d_out, int out_size)
{
    const float* x  = (const float*)d_in[0];
    const int*   tp = (const int*)d_in[1];
    const float* w0 = (const float*)d_in[2];
    const float* w1 = (const float*)d_in[3];
    const float* w2 = (const float*)d_in[4];
    const float* w3 = (const float*)d_in[5];
    float* out = (float*)d_out;

    const int gemm_smem = 3 * 32768 + 1024;   // 97 KB -> 2 CTAs/SM
    cudaFuncSetAttribute(gemm_qkv, cudaFuncAttributeMaxDynamicSharedMemorySize,
                         gemm_smem);
    cudaFuncSetAttribute(gemm_o, cudaFuncAttributeMaxDynamicSharedMemorySize,
                         gemm_smem);
    const int attn_smem = 64 * 1024 + 1024;   // KV double buffers only
    cudaFuncSetAttribute(attn_mma, cudaFuncAttributeMaxDynamicSharedMemorySize,
                         attn_smem);

    // 1) input/weight splits (hi/lo stored separately)
    xsplit_kernel<<<(Nv * Dv) / (4 * 256), 256>>>(x);
    wsplit_kernel<<<4 * (Dv * Dv) / (4 * 256), 256>>>(w0, w1, w2, w3);

    // 2) fused QKV projection; V epilogue writes transposed [bh][dk][s]
    gemm_qkv<<<dim3(24, Nv / 128), 256, gemm_smem>>>(tp);

    // 3) attention (writes hi/lo bf16 g_ash/g_asl directly)
    attn_mma<<<dim3(Sv / 128, Hv, Bv), 256, attn_smem>>>();

    // 4) output projection
    gemm_o<<<dim3(Dv / 128, Nv / 128), 256, gemm_smem>>>(out);
}

// round 15
// speedup vs baseline: 1.0426x; 1.0085x over previous
#include <cuda_runtime.h>
#include <cuda_bf16.h>
#include <math.h>
#include <stdint.h>

// Problem constants
#define Bv 2
#define Sv 2048
#define Dv 1024
#define Hv 16
#define DKv 64
#define Nv (Bv * Sv)     // 4096 rows
#define BHv (Bv * Hv)    // 32
#define NSLAB 48         // 3 terms x 16 K-chunks of 64

// ---------------------------------------------------------------------------
// Scratch (device globals — no cudaMalloc allowed). Hi/lo stored separately.
// ---------------------------------------------------------------------------
__device__ __nv_bfloat16 g_xh[(size_t)Nv * Dv];
__device__ __nv_bfloat16 g_xl[(size_t)Nv * Dv];
__device__ __nv_bfloat16 g_ash[(size_t)Nv * Dv];   // attention out hi
__device__ __nv_bfloat16 g_asl[(size_t)Nv * Dv];   // attention out lo
__device__ __nv_bfloat16 g_wh[4][(size_t)Dv * Dv];
__device__ __nv_bfloat16 g_wl[4][(size_t)Dv * Dv];
__device__ __nv_bfloat16 g_qh[(size_t)BHv * Sv * DKv];    // [bh][s][dk]
__device__ __nv_bfloat16 g_ql[(size_t)BHv * Sv * DKv];
__device__ __nv_bfloat16 g_kh[(size_t)BHv * Sv * DKv];
__device__ __nv_bfloat16 g_kl[(size_t)BHv * Sv * DKv];
__device__ __nv_bfloat16 g_vh[(size_t)BHv * DKv * Sv];    // [bh][dk][s]
__device__ __nv_bfloat16 g_vl[(size_t)BHv * DKv * Sv];

__device__ __forceinline__ uint32_t smem_to_u32(const void* p) {
    uint32_t a;
    asm("{ .reg .u64 t; cvta.to.shared.u64 t, %1; cvt.u32.u64 %0, t; }"
        : "=r"(a) : "l"(p));
    return a;
}
#define SW128(off) ((off) ^ (((off) >> 3) & 0x70))

__device__ __forceinline__ void ldm_x4(uint32_t* r, uint32_t addr) {
    asm volatile("ldmatrix.sync.aligned.m8n8.x4.shared.b16 {%0,%1,%2,%3}, [%4];"
        : "=r"(r[0]), "=r"(r[1]), "=r"(r[2]), "=r"(r[3]) : "r"(addr));
}
__device__ __forceinline__ void mma_16816(float* d, const uint32_t* a,
                                          const uint32_t* b) {
    asm volatile(
        "mma.sync.aligned.m16n8k16.row.col.f32.bf16.bf16.f32 "
        "{%0,%1,%2,%3}, {%4,%5,%6,%7}, {%8,%9}, {%0,%1,%2,%3};"
        : "+f"(d[0]), "+f"(d[1]), "+f"(d[2]), "+f"(d[3])
        : "r"(a[0]), "r"(a[1]), "r"(a[2]), "r"(a[3]), "r"(b[0]), "r"(b[1]));
}
__device__ __forceinline__ void cpa16(uint32_t dst, const void* src) {
    asm volatile("cp.async.cg.shared.global [%0], [%1], 16;"
        :: "r"(dst), "l"(src));
}
#define CP_COMMIT() asm volatile("cp.async.commit_group;" ::: "memory")
#define CP_WAIT(n)  asm volatile("cp.async.wait_group %0;" :: "n"(n) : "memory")

// split a float pair into hi/lo bf16x2 words
__device__ __forceinline__ void split2(float a, float b, uint32_t& h, uint32_t& l) {
    __nv_bfloat162 hp = __floats2bfloat162_rn(a, b);
    float r0 = __bfloat162float(hp.x), r1 = __bfloat162float(hp.y);
    __nv_bfloat162 lp = __floats2bfloat162_rn(a - r0, b - r1);
    h = *(uint32_t*)&hp;
    l = *(uint32_t*)&lp;
}

// ---------------------------------------------------------------------------
// Split fp32 -> separate hi/lo bf16 arrays (same [r][1024] layout)
// ---------------------------------------------------------------------------
__device__ __forceinline__ void split_body(
    const float* __restrict__ src, __nv_bfloat16* __restrict__ dh,
    __nv_bfloat16* __restrict__ dl, size_t e0)
{
    float4 v = *(const float4*)(src + e0);
    uint2 hu, lu;
    split2(v.x, v.y, hu.x, lu.x);
    split2(v.z, v.w, hu.y, lu.y);
    *(uint2*)(dh + e0) = hu;
    *(uint2*)(dl + e0) = lu;
}

__global__ __launch_bounds__(256) void xsplit_kernel(const float* __restrict__ x)
{
    size_t e0 = ((size_t)blockIdx.x * 256 + threadIdx.x) * 4;
    split_body(x, g_xh, g_xl, e0);
}

__global__ __launch_bounds__(256) void wsplit_kernel(
    const float* __restrict__ w0, const float* __restrict__ w1,
    const float* __restrict__ w2, const float* __restrict__ w3)
{
    int i = blockIdx.x >> 10;
    const float* src = (i == 0) ? w0 : (i == 1) ? w1 : (i == 2) ? w2 : w3;
    size_t e0 = ((size_t)(blockIdx.x & 1023) * 256 + threadIdx.x) * 4;
    split_body(src, g_wh[i], g_wl[i], e0);
}

// ---------------------------------------------------------------------------
// GEMM: 128x128 CTA tile, 48 slabs of K=64.
// Slab s: term t = s>>4 selects (Ah,Bh) / (Ah,Bl) / (Al,Bh); chunk k = s&15.
// 3-stage cp.async (32KB stages, 96KB -> 2 CTAs/SM), 1 sync per slab.
// mode: 0 = fp32 store; 1 = K RoPE split; 2 = Q RoPE*(0.125*log2e) split;
//       3 = V split written TRANSPOSED [bh][dk][s].
// ---------------------------------------------------------------------------
__device__ __forceinline__ void gemm_load_slab(
    const __nv_bfloat16* __restrict__ Ah, const __nv_bfloat16* __restrict__ Al,
    const __nv_bfloat16* __restrict__ Bh, const __nv_bfloat16* __restrict__ Bl,
    uint32_t bufu, int s, int tid)
{
    const int t = s >> 4;
    const int k = s & 15;
    const __nv_bfloat16* As = (t == 2) ? Al : Ah;
    const __nv_bfloat16* Bs = (t == 1) ? Bl : Bh;
    #pragma unroll
    for (int kk = 0; kk < 4; ++kk) {
        int idx = kk * 256 + tid;
        int r = idx >> 3, c = idx & 7;
        size_t goff = (size_t)r * Dv + k * 64 + c * 8;
        uint32_t so = SW128((uint32_t)(r * 128 + c * 16));
        cpa16(bufu + so,         As + goff);
        cpa16(bufu + 16384 + so, Bs + goff);
    }
}

__device__ __forceinline__ void gemm_tile(
    const __nv_bfloat16* __restrict__ Ah, const __nv_bfloat16* __restrict__ Al,
    const __nv_bfloat16* __restrict__ Bh, const __nv_bfloat16* __restrict__ Bl,
    const int* __restrict__ tp, int mode, int m0, int e0, uint32_t sbu,
    float* __restrict__ Y, __nv_bfloat16* __restrict__ dh,
    __nv_bfloat16* __restrict__ dl)
{
    const int tid = threadIdx.x;
    const int wid = tid >> 5;
    const int lane = tid & 31;
    const int wm = wid >> 1;
    const int wn = wid & 1;
    const int g2 = lane >> 2;
    const int t4 = lane & 3;
    const int lrow = lane & 15;
    const int lkoff = ((lane >> 4) & 1) * 16;

    float acc[2][8][4];
    #pragma unroll
    for (int i = 0; i < 2; ++i)
        #pragma unroll
        for (int j = 0; j < 8; ++j)
            #pragma unroll
            for (int k = 0; k < 4; ++k) acc[i][j][k] = 0.f;

    // prologue: slabs 0,1 -> stages 0,1
    gemm_load_slab(Ah, Al, Bh, Bl, sbu, 0, tid);
    CP_COMMIT();
    gemm_load_slab(Ah, Al, Bh, Bl, sbu + 32768, 1, tid);
    CP_COMMIT();

    int cc = 0;   // current stage = s % 3
    for (int s = 0; s < NSLAB; ++s) {
        if (s + 1 < NSLAB) { CP_WAIT(1); } else { CP_WAIT(0); }
        __syncthreads();
        if (s + 2 < NSLAB) {
            int nb = cc + 2; if (nb >= 3) nb -= 3;
            gemm_load_slab(Ah, Al, Bh, Bl, sbu + (uint32_t)(nb * 32768),
                           s + 2, tid);
            CP_COMMIT();
        }

        const uint32_t pAu = sbu + (uint32_t)(cc * 32768);
        const uint32_t pBu = pAu + 16384;
        #pragma unroll
        for (int ks = 0; ks < 4; ++ks) {
            const uint32_t kbyte = (uint32_t)(ks * 32 + lkoff);
            uint32_t afr[2][4], bfr[4][4];
            #pragma unroll
            for (int am = 0; am < 2; ++am) {
                uint32_t off = (uint32_t)((wm * 32 + am * 16 + lrow) * 128) + kbyte;
                ldm_x4(afr[am], pAu + SW128(off));
            }
            #pragma unroll
            for (int bn = 0; bn < 4; ++bn) {
                uint32_t off = (uint32_t)((wn * 64 + bn * 16 + lrow) * 128) + kbyte;
                ldm_x4(bfr[bn], pBu + SW128(off));
            }
            #pragma unroll
            for (int am = 0; am < 2; ++am)
                #pragma unroll
                for (int bn = 0; bn < 4; ++bn) {
                    uint32_t blo[2] = {bfr[bn][0], bfr[bn][2]};
                    uint32_t bhi[2] = {bfr[bn][1], bfr[bn][3]};
                    mma_16816(acc[am][bn * 2],     afr[am], blo);
                    mma_16816(acc[am][bn * 2 + 1], afr[am], bhi);
                }
        }
        ++cc; if (cc == 3) cc = 0;
    }

    // Q scale folds 1/sqrt(64) and log2(e) so attention can use exp2f.
    const float qs = (mode == 2) ? 0.18033688011112042f : 1.0f;
    const float LTH = 0.2878231366242557f;   // ln(10000)/32
    #pragma unroll
    for (int am = 0; am < 2; ++am) {
        #pragma unroll
        for (int half = 0; half < 2; ++half) {
            int m = m0 + wm * 32 + am * 16 + g2 + half * 8;
            int sr = m & (Sv - 1);
            float pos = (mode == 1 || mode == 2) ? (float)tp[sr] : 0.f;
            #pragma unroll
            for (int bn = 0; bn < 8; ++bn) {
                int e = e0 + wn * 64 + bn * 8 + t4 * 2;
                float d0 = acc[am][bn][half * 2];
                float d1 = acc[am][bn][half * 2 + 1];
                if (mode == 1 || mode == 2) {
                    int p = (e & (DKv - 1)) >> 1;
                    float inv = expf(-LTH * (float)p);
                    float sn, cs;
                    sincosf(pos * inv, &sn, &cs);
                    float o0 = (cs * d0 - sn * d1) * qs;
                    float o1 = (sn * d0 + cs * d1) * qs;
                    d0 = o0; d1 = o1;
                }
                if (mode == 0) {
                    *(float2*)(Y + (size_t)m * Dv + e) = make_float2(d0, d1);
                } else if (mode == 3) {
                    // V: write hi/lo transposed [bh][dk][s] directly
                    int bh = (m >> 11) * Hv + (e >> 6);
                    int dk = e & (DKv - 1);
                    size_t idx = ((size_t)bh * DKv + dk) * Sv + sr;
                    uint32_t h, l;
                    split2(d0, d1, h, l);
                    *(uint16_t*)((uint16_t*)g_vh + idx)      = (uint16_t)h;
                    *(uint16_t*)((uint16_t*)g_vh + idx + Sv) = (uint16_t)(h >> 16);
                    *(uint16_t*)((uint16_t*)g_vl + idx)      = (uint16_t)l;
                    *(uint16_t*)((uint16_t*)g_vl + idx + Sv) = (uint16_t)(l >> 16);
                } else {
                    int bh = (m >> 11) * Hv + (e >> 6);
                    int dk = e & (DKv - 1);
                    size_t idx = ((size_t)bh * Sv + sr) * DKv + dk;
                    uint32_t h, l;
                    split2(d0, d1, h, l);
                    *(uint32_t*)(dh + idx) = h;
                    *(uint32_t*)(dl + idx) = l;
                }
            }
        }
    }
}

// Fused QKV projection: grid (24, 32); region = blockIdx.x >> 3 (0=Q,1=K,2=V)
__global__ __launch_bounds__(256, 2) void gemm_qkv(const int* __restrict__ tp)
{
    extern __shared__ char smraw[];
    uint32_t su = smem_to_u32(smraw);
    uint32_t sbu = (su + 1023u) & ~1023u;

    const int region = blockIdx.x >> 3;
    const int e0 = (blockIdx.x & 7) * 128;
    const int m0 = blockIdx.y * 128;
    const __nv_bfloat16* Ah = g_xh + (size_t)m0 * Dv;
    const __nv_bfloat16* Al = g_xl + (size_t)m0 * Dv;
    const __nv_bfloat16* Bh = g_wh[region] + (size_t)e0 * Dv;
    const __nv_bfloat16* Bl = g_wl[region] + (size_t)e0 * Dv;
    __nv_bfloat16* dh = (region == 0) ? g_qh : g_kh;
    __nv_bfloat16* dl = (region == 0) ? g_ql : g_kl;
    const int mode = (region == 0) ? 2 : (region == 1) ? 1 : 3;
    gemm_tile(Ah, Al, Bh, Bl, tp, mode, m0, e0, sbu, (float*)0, dh, dl);
}

// Output projection: grid (8, 32)
__global__ __launch_bounds__(256, 2) void gemm_o(float* __restrict__ out)
{
    extern __shared__ char smraw[];
    uint32_t su = smem_to_u32(smraw);
    uint32_t sbu = (su + 1023u) & ~1023u;

    const int e0 = blockIdx.x * 128;
    const int m0 = blockIdx.y * 128;
    gemm_tile(g_ash + (size_t)m0 * Dv, g_asl + (size_t)m0 * Dv,
              g_wh[3] + (size_t)e0 * Dv, g_wl[3] + (size_t)e0 * Dv,
              (const int*)0, 0, m0, e0, sbu, out,
              (__nv_bfloat16*)0, (__nv_bfloat16*)0);
}

// ---------------------------------------------------------------------------
// Flash attention on mma.sync, 3-term split for QK^T AND PV (R13 math —
// dropping Plo*Vhi measured 1.2e-3, over threshold). exp2f softmax.
// Fully-masked half-tiles (last kv tile, warps 0-3) skipped exactly.
// ---------------------------------------------------------------------------
__device__ __forceinline__ void attn_load_tile(
    uint32_t sb, int bh, int j, int buf, int tid)
{
    const uint32_t oKh = 0, oKl = 16384, oVh = 32768, oVl = 49152;
    const char* kh = (const char*)(g_kh + ((size_t)bh * Sv + j * 64) * 64);
    const char* kl = (const char*)(g_kl + ((size_t)bh * Sv + j * 64) * 64);
    #pragma unroll
    for (int p = 0; p < 2; ++p) {
        int idx = p * 256 + tid;
        int r = idx >> 3, c = idx & 7;
        uint32_t so = SW128((uint32_t)(r * 128 + c * 16));
        uint32_t bo = (uint32_t)(buf * 8192);
        cpa16(sb + oKh + bo + so, kh + idx * 16);
        cpa16(sb + oKl + bo + so, kl + idx * 16);
        const char* vh = (const char*)(g_vh + ((size_t)bh * 64 + r) * Sv + j * 64);
        const char* vl = (const char*)(g_vl + ((size_t)bh * 64 + r) * Sv + j * 64);
        cpa16(sb + oVh + bo + so, vh + c * 16);
        cpa16(sb + oVl + bo + so, vl + c * 16);
    }
}

__global__ __launch_bounds__(256, 1) void attn_mma()
{
    extern __shared__ char smraw[];
    uint32_t su = smem_to_u32(smraw);
    uint32_t sb = (su + 1023u) & ~1023u;
    const uint32_t oKh = 0, oKl = 16384, oVh = 32768, oVl = 49152;

    const int tid = threadIdx.x;
    const int wid = tid >> 5, lane = tid & 31;
    const int g2 = lane >> 2, t4 = lane & 3;
    const int lrow = lane & 15;
    const int lkoff = ((lane >> 4) & 1) * 16;

    const int qt = gridDim.x - 1 - blockIdx.x;   // big tiles first
    const int h = blockIdx.y, b = blockIdx.z;
    const int bh = b * Hv + h;
    const int q0 = qt * 128;
    const int jmax = 2 * qt + 1;

    // --- stage Q through smem (reusing K buffer space), hoist frags to regs
    uint32_t qfh[4][4], qfl[4][4];
    {
        const char* qh = (const char*)(g_qh + ((size_t)bh * Sv + q0) * 64);
        const char* ql = (const char*)(g_ql + ((size_t)bh * Sv + q0) * 64);
        #pragma unroll
        for (int p = 0; p < 4; ++p) {
            int idx = p * 256 + tid;
            uint32_t so = SW128((uint32_t)(idx * 16));
            cpa16(sb + so,         qh + idx * 16);
            cpa16(sb + 16384 + so, ql + idx * 16);
        }
        CP_COMMIT();
        CP_WAIT(0);
        __syncthreads();
        #pragma unroll
        for (int ks = 0; ks < 4; ++ks) {
            uint32_t aoff =
                SW128((uint32_t)((wid * 16 + lrow) * 128 + ks * 32 + lkoff));
            ldm_x4(qfh[ks], sb + aoff);
            ldm_x4(qfl[ks], sb + 16384 + aoff);
        }
        __syncthreads();
        attn_load_tile(sb, bh, 0, 0, tid);
        CP_COMMIT();
    }

    float m0 = -1e30f, m1 = -1e30f, l0 = 0.f, l1 = 0.f;
    float oacc[8][4];
    #pragma unroll
    for (int i = 0; i < 8; ++i)
        #pragma unroll
        for (int c = 0; c < 4; ++c) oacc[i][c] = 0.f;

    for (int j = 0; j <= jmax; ++j) {
        const int cur = j & 1;
        CP_WAIT(0);
        __syncthreads();
        if (j < jmax) {
            attn_load_tile(sb, bh, j + 1, cur ^ 1, tid);
            CP_COMMIT();
        }

        // Last tile: warps 0-3 (rows q0..q0+63) are fully above the causal
        // diagonal (cols >= q0+64) -> P==0, state unchanged. Skip exactly.
        if (j == jmax && wid < 4) continue;

        // S = Qhi*Khi + Qhi*Klo + Qlo*Khi (Q frags in regs)
        float sacc[8][4];
        #pragma unroll
        for (int i = 0; i < 8; ++i)
            #pragma unroll
            for (int c = 0; c < 4; ++c) sacc[i][c] = 0.f;
        {
            const uint32_t kb = (uint32_t)(cur * 8192);
            const uint32_t khB = sb + oKh + kb, klB = sb + oKl + kb;
            #pragma unroll
            for (int ks = 0; ks < 4; ++ks) {
                uint32_t kbyte = (uint32_t)(ks * 32 + lkoff);
                #pragma unroll
                for (int bn4 = 0; bn4 < 4; ++bn4) {
                    uint32_t boff = SW128((uint32_t)((bn4 * 16 + lrow) * 128) + kbyte);
                    uint32_t bh_[4], bl_[4];
                    ldm_x4(bh_, khB + boff);
                    ldm_x4(bl_, klB + boff);
                    uint32_t bhl[2] = {bh_[0], bh_[2]}, bhh[2] = {bh_[1], bh_[3]};
                    uint32_t bll[2] = {bl_[0], bl_[2]}, blh[2] = {bl_[1], bl_[3]};
                    mma_16816(sacc[2 * bn4],     qfh[ks], bhl);
                    mma_16816(sacc[2 * bn4 + 1], qfh[ks], bhh);
                    mma_16816(sacc[2 * bn4],     qfh[ks], bll);
                    mma_16816(sacc[2 * bn4 + 1], qfh[ks], blh);
                    mma_16816(sacc[2 * bn4],     qfl[ks], bhl);
                    mma_16816(sacc[2 * bn4 + 1], qfl[ks], bhh);
                }
            }
        }

        if (j >= 2 * qt) {
            int r0 = q0 + wid * 16 + g2;
            #pragma unroll
            for (int bn = 0; bn < 8; ++bn) {
                int col = j * 64 + bn * 8 + 2 * t4;
                #pragma unroll
                for (int c = 0; c < 4; ++c) {
                    int row = r0 + ((c >= 2) ? 8 : 0);
                    if (col + (c & 1) > row) sacc[bn][c] = -1e30f;
                }
            }
        }

        float tm0 = -1e30f, tm1 = -1e30f;
        #pragma unroll
        for (int bn = 0; bn < 8; ++bn) {
            tm0 = fmaxf(tm0, fmaxf(sacc[bn][0], sacc[bn][1]));
            tm1 = fmaxf(tm1, fmaxf(sacc[bn][2], sacc[bn][3]));
        }
        tm0 = fmaxf(tm0, __shfl_xor_sync(0xffffffffu, tm0, 1));
        tm0 = fmaxf(tm0, __shfl_xor_sync(0xffffffffu, tm0, 2));
        tm1 = fmaxf(tm1, __shfl_xor_sync(0xffffffffu, tm1, 1));
        tm1 = fmaxf(tm1, __shfl_xor_sync(0xffffffffu, tm1, 2));
        float mn0 = fmaxf(m0, tm0), mn1 = fmaxf(m1, tm1);
        float sc0 = exp2f(m0 - mn0), sc1 = exp2f(m1 - mn1);
        float rs0 = 0.f, rs1 = 0.f;
        #pragma unroll
        for (int bn = 0; bn < 8; ++bn) {
            sacc[bn][0] = exp2f(sacc[bn][0] - mn0);
            sacc[bn][1] = exp2f(sacc[bn][1] - mn0);
            sacc[bn][2] = exp2f(sacc[bn][2] - mn1);
            sacc[bn][3] = exp2f(sacc[bn][3] - mn1);
            rs0 += sacc[bn][0] + sacc[bn][1];
            rs1 += sacc[bn][2] + sacc[bn][3];
        }
        rs0 += __shfl_xor_sync(0xffffffffu, rs0, 1);
        rs0 += __shfl_xor_sync(0xffffffffu, rs0, 2);
        rs1 += __shfl_xor_sync(0xffffffffu, rs1, 1);
        rs1 += __shfl_xor_sync(0xffffffffu, rs1, 2);
        l0 = l0 * sc0 + rs0;
        l1 = l1 * sc1 + rs1;
        m0 = mn0; m1 = mn1;
        #pragma unroll
        for (int bn = 0; bn < 8; ++bn) {
            oacc[bn][0] *= sc0; oacc[bn][1] *= sc0;
            oacc[bn][2] *= sc1; oacc[bn][3] *= sc1;
        }

        // O += Phi*Vhi + Phi*Vlo + Plo*Vhi
        {
            uint32_t vhB = sb + oVh + (uint32_t)(cur * 8192);
            uint32_t vlB = sb + oVl + (uint32_t)(cur * 8192);
            #pragma unroll
            for (int ks = 0; ks < 4; ++ks) {
                uint32_t ah[4], al[4];
                #pragma unroll
                for (int q = 0; q < 4; ++q) {
                    int tl = 2 * ks + (q >> 1);
                    int c0 = (q & 1) * 2;
                    split2(sacc[tl][c0], sacc[tl][c0 + 1], ah[q], al[q]);
                }
                uint32_t kbyte = (uint32_t)(ks * 32 + lkoff);
                #pragma unroll
                for (int bn4 = 0; bn4 < 4; ++bn4) {
                    uint32_t bH[4], bL[4];
                    uint32_t off = SW128((uint32_t)((bn4 * 16 + lrow) * 128) + kbyte);
                    ldm_x4(bH, vhB + off);
                    ldm_x4(bL, vlB + off);
                    uint32_t bHl[2] = {bH[0], bH[2]}, bHh[2] = {bH[1], bH[3]};
                    uint32_t bLl[2] = {bL[0], bL[2]}, bLh[2] = {bL[1], bL[3]};
                    mma_16816(oacc[2 * bn4],     ah, bHl);
                    mma_16816(oacc[2 * bn4 + 1], ah, bHh);
                    mma_16816(oacc[2 * bn4],     ah, bLl);
                    mma_16816(oacc[2 * bn4 + 1], ah, bLh);
                    mma_16816(oacc[2 * bn4],     al, bHl);
                    mma_16816(oacc[2 * bn4 + 1], al, bHh);
                }
            }
        }
    }

    float il0 = 1.f / l0, il1 = 1.f / l1;
    int row0 = q0 + wid * 16 + g2;
    size_t n0 = (size_t)b * Sv + row0;
    #pragma unroll
    for (int bn = 0; bn < 8; ++bn) {
        int col = h * 64 + bn * 8 + 2 * t4;
        #pragma unroll
        for (int half = 0; half < 2; ++half) {
            float v0 = oacc[bn][half * 2]     * (half ? il1 : il0);
            float v1 = oacc[bn][half * 2 + 1] * (half ? il1 : il0);
            uint32_t hp, lp;
            split2(v0, v1, hp, lp);
            size_t base = (n0 + half * 8) * Dv + col;
            *(uint32_t*)(g_ash + base) = hp;
            *(uint32_t*)(g_asl + base) = lp;
        }
    }
}

// ---------------------------------------------------------------------------
extern "C" void kernel_launch(void* const* d_in, const int* in_sizes, int n_in,
                              void* d_out, int out_size)
{
    const float* x  = (const float*)d_in[0];
    const int*   tp = (const int*)d_in[1];
    const float* w0 = (const float*)d_in[2];
    const float* w1 = (const float*)d_in[3];
    const float* w2 = (const float*)d_in[4];
    const float* w3 = (const float*)d_in[5];
    float* out = (float*)d_out;

    const int gemm_smem = 3 * 32768 + 1024;   // 97 KB -> 2 CTAs/SM
    cudaFuncSetAttribute(gemm_qkv, cudaFuncAttributeMaxDynamicSharedMemorySize,
                         gemm_smem);
    cudaFuncSetAttribute(gemm_o, cudaFuncAttributeMaxDynamicSharedMemorySize,
                         gemm_smem);
    const int attn_smem = 64 * 1024 + 1024;   // KV double buffers only
    cudaFuncSetAttribute(attn_mma, cudaFuncAttributeMaxDynamicSharedMemorySize,
                         attn_smem);

    // 1) input/weight splits (hi/lo stored separately)
    xsplit_kernel<<<(Nv * Dv) / (4 * 256), 256>>>(x);
    wsplit_kernel<<<4 * (Dv * Dv) / (4 * 256), 256>>>(w0, w1, w2, w3);

    // 2) fused QKV projection; V epilogue writes transposed [bh][dk][s]
    gemm_qkv<<<dim3(24, Nv / 128), 256, gemm_smem>>>(tp);

    // 3) attention (writes hi/lo bf16 g_ash/g_asl directly)
    attn_mma<<<dim3(Sv / 128, Hv, Bv), 256, attn_smem>>>();

    // 4) output projection
    gemm_o<<<dim3(Dv / 128, Nv / 128), 256, gemm_smem>>>(out);
}

// round 16
// speedup vs baseline: 1.0827x; 1.0385x over previous
#include <cuda_runtime.h>
#include <cuda_bf16.h>
#include <math.h>
#include <stdint.h>

// Problem constants
#define Bv 2
#define Sv 2048
#define Dv 1024
#define Hv 16
#define DKv 64
#define Nv (Bv * Sv)     // 4096 rows
#define BHv (Bv * Hv)    // 32
#define NSLAB 48         // 3 terms x 16 K-chunks of 64

// ---------------------------------------------------------------------------
// Scratch (device globals — no cudaMalloc allowed). Hi/lo stored separately.
// ---------------------------------------------------------------------------
__device__ __nv_bfloat16 g_xh[(size_t)Nv * Dv];
__device__ __nv_bfloat16 g_xl[(size_t)Nv * Dv];
__device__ __nv_bfloat16 g_ash[(size_t)Nv * Dv];   // attention out hi
__device__ __nv_bfloat16 g_asl[(size_t)Nv * Dv];   // attention out lo
__device__ __nv_bfloat16 g_wh[4][(size_t)Dv * Dv];
__device__ __nv_bfloat16 g_wl[4][(size_t)Dv * Dv];
__device__ __nv_bfloat16 g_qh[(size_t)BHv * Sv * DKv];    // [bh][s][dk]
__device__ __nv_bfloat16 g_ql[(size_t)BHv * Sv * DKv];
__device__ __nv_bfloat16 g_kh[(size_t)BHv * Sv * DKv];
__device__ __nv_bfloat16 g_kl[(size_t)BHv * Sv * DKv];
__device__ __nv_bfloat16 g_vh[(size_t)BHv * DKv * Sv];    // [bh][dk][s]
__device__ __nv_bfloat16 g_vl[(size_t)BHv * DKv * Sv];

__device__ __forceinline__ uint32_t smem_to_u32(const void* p) {
    uint32_t a;
    asm("{ .reg .u64 t; cvta.to.shared.u64 t, %1; cvt.u32.u64 %0, t; }"
        : "=r"(a) : "l"(p));
    return a;
}
#define SW128(off) ((off) ^ (((off) >> 3) & 0x70))

__device__ __forceinline__ void ldm_x4(uint32_t* r, uint32_t addr) {
    asm volatile("ldmatrix.sync.aligned.m8n8.x4.shared.b16 {%0,%1,%2,%3}, [%4];"
        : "=r"(r[0]), "=r"(r[1]), "=r"(r[2]), "=r"(r[3]) : "r"(addr));
}
__device__ __forceinline__ void mma_16816(float* d, const uint32_t* a,
                                          const uint32_t* b) {
    asm volatile(
        "mma.sync.aligned.m16n8k16.row.col.f32.bf16.bf16.f32 "
        "{%0,%1,%2,%3}, {%4,%5,%6,%7}, {%8,%9}, {%0,%1,%2,%3};"
        : "+f"(d[0]), "+f"(d[1]), "+f"(d[2]), "+f"(d[3])
        : "r"(a[0]), "r"(a[1]), "r"(a[2]), "r"(a[3]), "r"(b[0]), "r"(b[1]));
}
__device__ __forceinline__ void cpa16(uint32_t dst, const void* src) {
    asm volatile("cp.async.cg.shared.global [%0], [%1], 16;"
        :: "r"(dst), "l"(src));
}
#define CP_COMMIT() asm volatile("cp.async.commit_group;" ::: "memory")
#define CP_WAIT(n)  asm volatile("cp.async.wait_group %0;" :: "n"(n) : "memory")

// split a float pair into hi/lo bf16x2 words
__device__ __forceinline__ void split2(float a, float b, uint32_t& h, uint32_t& l) {
    __nv_bfloat162 hp = __floats2bfloat162_rn(a, b);
    float r0 = __bfloat162float(hp.x), r1 = __bfloat162float(hp.y);
    __nv_bfloat162 lp = __floats2bfloat162_rn(a - r0, b - r1);
    h = *(uint32_t*)&hp;
    l = *(uint32_t*)&lp;
}

// ---------------------------------------------------------------------------
// Split fp32 -> separate hi/lo bf16 arrays (same [r][1024] layout)
// ---------------------------------------------------------------------------
__device__ __forceinline__ void split_body(
    const float* __restrict__ src, __nv_bfloat16* __restrict__ dh,
    __nv_bfloat16* __restrict__ dl, size_t e0)
{
    float4 v = *(const float4*)(src + e0);
    uint2 hu, lu;
    split2(v.x, v.y, hu.x, lu.x);
    split2(v.z, v.w, hu.y, lu.y);
    *(uint2*)(dh + e0) = hu;
    *(uint2*)(dl + e0) = lu;
}

__global__ __launch_bounds__(256) void xsplit_kernel(const float* __restrict__ x)
{
    size_t e0 = ((size_t)blockIdx.x * 256 + threadIdx.x) * 4;
    split_body(x, g_xh, g_xl, e0);
}

__global__ __launch_bounds__(256) void wsplit_kernel(
    const float* __restrict__ w0, const float* __restrict__ w1,
    const float* __restrict__ w2, const float* __restrict__ w3)
{
    int i = blockIdx.x >> 10;
    const float* src = (i == 0) ? w0 : (i == 1) ? w1 : (i == 2) ? w2 : w3;
    size_t e0 = ((size_t)(blockIdx.x & 1023) * 256 + threadIdx.x) * 4;
    split_body(src, g_wh[i], g_wl[i], e0);
}

// ---------------------------------------------------------------------------
// GEMM: 128x128 CTA tile, 48 slabs of K=64 (unchanged, proven).
// mode: 0 = fp32 store; 1 = K RoPE split; 2 = Q RoPE*(0.125*log2e) split;
//       3 = V split written TRANSPOSED [bh][dk][s].
// ---------------------------------------------------------------------------
__device__ __forceinline__ void gemm_load_slab(
    const __nv_bfloat16* __restrict__ Ah, const __nv_bfloat16* __restrict__ Al,
    const __nv_bfloat16* __restrict__ Bh, const __nv_bfloat16* __restrict__ Bl,
    uint32_t bufu, int s, int tid)
{
    const int t = s >> 4;
    const int k = s & 15;
    const __nv_bfloat16* As = (t == 2) ? Al : Ah;
    const __nv_bfloat16* Bs = (t == 1) ? Bl : Bh;
    #pragma unroll
    for (int kk = 0; kk < 4; ++kk) {
        int idx = kk * 256 + tid;
        int r = idx >> 3, c = idx & 7;
        size_t goff = (size_t)r * Dv + k * 64 + c * 8;
        uint32_t so = SW128((uint32_t)(r * 128 + c * 16));
        cpa16(bufu + so,         As + goff);
        cpa16(bufu + 16384 + so, Bs + goff);
    }
}

__device__ __forceinline__ void gemm_tile(
    const __nv_bfloat16* __restrict__ Ah, const __nv_bfloat16* __restrict__ Al,
    const __nv_bfloat16* __restrict__ Bh, const __nv_bfloat16* __restrict__ Bl,
    const int* __restrict__ tp, int mode, int m0, int e0, uint32_t sbu,
    float* __restrict__ Y, __nv_bfloat16* __restrict__ dh,
    __nv_bfloat16* __restrict__ dl)
{
    const int tid = threadIdx.x;
    const int wid = tid >> 5;
    const int lane = tid & 31;
    const int wm = wid >> 1;
    const int wn = wid & 1;
    const int g2 = lane >> 2;
    const int t4 = lane & 3;
    const int lrow = lane & 15;
    const int lkoff = ((lane >> 4) & 1) * 16;

    float acc[2][8][4];
    #pragma unroll
    for (int i = 0; i < 2; ++i)
        #pragma unroll
        for (int j = 0; j < 8; ++j)
            #pragma unroll
            for (int k = 0; k < 4; ++k) acc[i][j][k] = 0.f;

    gemm_load_slab(Ah, Al, Bh, Bl, sbu, 0, tid);
    CP_COMMIT();
    gemm_load_slab(Ah, Al, Bh, Bl, sbu + 32768, 1, tid);
    CP_COMMIT();

    int cc = 0;
    for (int s = 0; s < NSLAB; ++s) {
        if (s + 1 < NSLAB) { CP_WAIT(1); } else { CP_WAIT(0); }
        __syncthreads();
        if (s + 2 < NSLAB) {
            int nb = cc + 2; if (nb >= 3) nb -= 3;
            gemm_load_slab(Ah, Al, Bh, Bl, sbu + (uint32_t)(nb * 32768),
                           s + 2, tid);
            CP_COMMIT();
        }

        const uint32_t pAu = sbu + (uint32_t)(cc * 32768);
        const uint32_t pBu = pAu + 16384;
        #pragma unroll
        for (int ks = 0; ks < 4; ++ks) {
            const uint32_t kbyte = (uint32_t)(ks * 32 + lkoff);
            uint32_t afr[2][4], bfr[4][4];
            #pragma unroll
            for (int am = 0; am < 2; ++am) {
                uint32_t off = (uint32_t)((wm * 32 + am * 16 + lrow) * 128) + kbyte;
                ldm_x4(afr[am], pAu + SW128(off));
            }
            #pragma unroll
            for (int bn = 0; bn < 4; ++bn) {
                uint32_t off = (uint32_t)((wn * 64 + bn * 16 + lrow) * 128) + kbyte;
                ldm_x4(bfr[bn], pBu + SW128(off));
            }
            #pragma unroll
            for (int am = 0; am < 2; ++am)
                #pragma unroll
                for (int bn = 0; bn < 4; ++bn) {
                    uint32_t blo[2] = {bfr[bn][0], bfr[bn][2]};
                    uint32_t bhi[2] = {bfr[bn][1], bfr[bn][3]};
                    mma_16816(acc[am][bn * 2],     afr[am], blo);
                    mma_16816(acc[am][bn * 2 + 1], afr[am], bhi);
                }
        }
        ++cc; if (cc == 3) cc = 0;
    }

    // Q scale folds 1/sqrt(64) and log2(e) so attention can use exp2f.
    const float qs = (mode == 2) ? 0.18033688011112042f : 1.0f;
    const float LTH = 0.2878231366242557f;   // ln(10000)/32
    #pragma unroll
    for (int am = 0; am < 2; ++am) {
        #pragma unroll
        for (int half = 0; half < 2; ++half) {
            int m = m0 + wm * 32 + am * 16 + g2 + half * 8;
            int sr = m & (Sv - 1);
            float pos = (mode == 1 || mode == 2) ? (float)tp[sr] : 0.f;
            #pragma unroll
            for (int bn = 0; bn < 8; ++bn) {
                int e = e0 + wn * 64 + bn * 8 + t4 * 2;
                float d0 = acc[am][bn][half * 2];
                float d1 = acc[am][bn][half * 2 + 1];
                if (mode == 1 || mode == 2) {
                    int p = (e & (DKv - 1)) >> 1;
                    float inv = expf(-LTH * (float)p);
                    float sn, cs;
                    sincosf(pos * inv, &sn, &cs);
                    float o0 = (cs * d0 - sn * d1) * qs;
                    float o1 = (sn * d0 + cs * d1) * qs;
                    d0 = o0; d1 = o1;
                }
                if (mode == 0) {
                    *(float2*)(Y + (size_t)m * Dv + e) = make_float2(d0, d1);
                } else if (mode == 3) {
                    int bh = (m >> 11) * Hv + (e >> 6);
                    int dk = e & (DKv - 1);
                    size_t idx = ((size_t)bh * DKv + dk) * Sv + sr;
                    uint32_t h, l;
                    split2(d0, d1, h, l);
                    *(uint16_t*)((uint16_t*)g_vh + idx)      = (uint16_t)h;
                    *(uint16_t*)((uint16_t*)g_vh + idx + Sv) = (uint16_t)(h >> 16);
                    *(uint16_t*)((uint16_t*)g_vl + idx)      = (uint16_t)l;
                    *(uint16_t*)((uint16_t*)g_vl + idx + Sv) = (uint16_t)(l >> 16);
                } else {
                    int bh = (m >> 11) * Hv + (e >> 6);
                    int dk = e & (DKv - 1);
                    size_t idx = ((size_t)bh * Sv + sr) * DKv + dk;
                    uint32_t h, l;
                    split2(d0, d1, h, l);
                    *(uint32_t*)(dh + idx) = h;
                    *(uint32_t*)(dl + idx) = l;
                }
            }
        }
    }
}

// Fused QKV projection: grid (24, 32); region = blockIdx.x >> 3 (0=Q,1=K,2=V)
__global__ __launch_bounds__(256, 2) void gemm_qkv(const int* __restrict__ tp)
{
    extern __shared__ char smraw[];
    uint32_t su = smem_to_u32(smraw);
    uint32_t sbu = (su + 1023u) & ~1023u;

    const int region = blockIdx.x >> 3;
    const int e0 = (blockIdx.x & 7) * 128;
    const int m0 = blockIdx.y * 128;
    const __nv_bfloat16* Ah = g_xh + (size_t)m0 * Dv;
    const __nv_bfloat16* Al = g_xl + (size_t)m0 * Dv;
    const __nv_bfloat16* Bh = g_wh[region] + (size_t)e0 * Dv;
    const __nv_bfloat16* Bl = g_wl[region] + (size_t)e0 * Dv;
    __nv_bfloat16* dh = (region == 0) ? g_qh : g_kh;
    __nv_bfloat16* dl = (region == 0) ? g_ql : g_kl;
    const int mode = (region == 0) ? 2 : (region == 1) ? 1 : 3;
    gemm_tile(Ah, Al, Bh, Bl, tp, mode, m0, e0, sbu, (float*)0, dh, dl);
}

// Output projection: grid (8, 32)
__global__ __launch_bounds__(256, 2) void gemm_o(float* __restrict__ out)
{
    extern __shared__ char smraw[];
    uint32_t su = smem_to_u32(smraw);
    uint32_t sbu = (su + 1023u) & ~1023u;

    const int e0 = blockIdx.x * 128;
    const int m0 = blockIdx.y * 128;
    gemm_tile(g_ash + (size_t)m0 * Dv, g_asl + (size_t)m0 * Dv,
              g_wh[3] + (size_t)e0 * Dv, g_wl[3] + (size_t)e0 * Dv,
              (const int*)0, 0, m0, e0, sbu, out,
              (__nv_bfloat16*)0, (__nv_bfloat16*)0);
}

// ---------------------------------------------------------------------------
// Flash attention on mma.sync, 3-term split for QK^T and PV, exp2f softmax.
// CTA = 128 threads (4 warps), q-tile 64 rows -> ~26K regs/CTA -> 2 CTAs/SM
// of independent work (cross-CTA latency hiding). KV tiles 64, double-buffered.
// ---------------------------------------------------------------------------
__device__ __forceinline__ void attn_load_tile(
    uint32_t sb, int bh, int j, int buf, int tid)
{
    const uint32_t oKh = 0, oKl = 16384, oVh = 32768, oVl = 49152;
    const char* kh = (const char*)(g_kh + ((size_t)bh * Sv + j * 64) * 64);
    const char* kl = (const char*)(g_kl + ((size_t)bh * Sv + j * 64) * 64);
    #pragma unroll
    for (int p = 0; p < 4; ++p) {
        int idx = p * 128 + tid;      // 0..511 chunks of 16B
        int r = idx >> 3, c = idx & 7;
        uint32_t so = SW128((uint32_t)(r * 128 + c * 16));
        uint32_t bo = (uint32_t)(buf * 8192);
        cpa16(sb + oKh + bo + so, kh + idx * 16);
        cpa16(sb + oKl + bo + so, kl + idx * 16);
        const char* vh = (const char*)(g_vh + ((size_t)bh * 64 + r) * Sv + j * 64);
        const char* vl = (const char*)(g_vl + ((size_t)bh * 64 + r) * Sv + j * 64);
        cpa16(sb + oVh + bo + so, vh + c * 16);
        cpa16(sb + oVl + bo + so, vl + c * 16);
    }
}

__global__ __launch_bounds__(128, 1) void attn_mma()
{
    extern __shared__ char smraw[];
    uint32_t su = smem_to_u32(smraw);
    uint32_t sb = (su + 1023u) & ~1023u;
    const uint32_t oKh = 0, oKl = 16384, oVh = 32768, oVl = 49152;

    const int tid = threadIdx.x;
    const int wid = tid >> 5, lane = tid & 31;
    const int g2 = lane >> 2, t4 = lane & 3;
    const int lrow = lane & 15;
    const int lkoff = ((lane >> 4) & 1) * 16;

    const int qt = gridDim.x - 1 - blockIdx.x;   // big tiles first
    const int h = blockIdx.y, b = blockIdx.z;
    const int bh = b * Hv + h;
    const int q0 = qt * 64;
    const int jmax = qt;

    // --- stage Q through smem (reusing K buffer space), hoist frags to regs
    uint32_t qfh[4][4], qfl[4][4];
    {
        const char* qh = (const char*)(g_qh + ((size_t)bh * Sv + q0) * 64);
        const char* ql = (const char*)(g_ql + ((size_t)bh * Sv + q0) * 64);
        #pragma unroll
        for (int p = 0; p < 4; ++p) {
            int idx = p * 128 + tid;   // 0..511 chunks (64x64 bf16 = 8KB)
            uint32_t so = SW128((uint32_t)(idx * 16));
            cpa16(sb + so,        qh + idx * 16);
            cpa16(sb + 8192 + so, ql + idx * 16);
        }
        CP_COMMIT();
        CP_WAIT(0);
        __syncthreads();
        #pragma unroll
        for (int ks = 0; ks < 4; ++ks) {
            uint32_t aoff =
                SW128((uint32_t)((wid * 16 + lrow) * 128 + ks * 32 + lkoff));
            ldm_x4(qfh[ks], sb + aoff);
            ldm_x4(qfl[ks], sb + 8192 + aoff);
        }
        __syncthreads();
        attn_load_tile(sb, bh, 0, 0, tid);
        CP_COMMIT();
    }

    float m0 = -1e30f, m1 = -1e30f, l0 = 0.f, l1 = 0.f;
    float oacc[8][4];
    #pragma unroll
    for (int i = 0; i < 8; ++i)
        #pragma unroll
        for (int c = 0; c < 4; ++c) oacc[i][c] = 0.f;

    for (int j = 0; j <= jmax; ++j) {
        const int cur = j & 1;
        CP_WAIT(0);
        __syncthreads();
        if (j < jmax) {
            attn_load_tile(sb, bh, j + 1, cur ^ 1, tid);
            CP_COMMIT();
        }

        // S = Qhi*Khi + Qhi*Klo + Qlo*Khi (Q frags in regs)
        float sacc[8][4];
        #pragma unroll
        for (int i = 0; i < 8; ++i)
            #pragma unroll
            for (int c = 0; c < 4; ++c) sacc[i][c] = 0.f;
        {
            const uint32_t kb = (uint32_t)(cur * 8192);
            const uint32_t khB = sb + oKh + kb, klB = sb + oKl + kb;
            #pragma unroll
            for (int ks = 0; ks < 4; ++ks) {
                uint32_t kbyte = (uint32_t)(ks * 32 + lkoff);
                #pragma unroll
                for (int bn4 = 0; bn4 < 4; ++bn4) {
                    uint32_t boff = SW128((uint32_t)((bn4 * 16 + lrow) * 128) + kbyte);
                    uint32_t bh_[4], bl_[4];
                    ldm_x4(bh_, khB + boff);
                    ldm_x4(bl_, klB + boff);
                    uint32_t bhl[2] = {bh_[0], bh_[2]}, bhh[2] = {bh_[1], bh_[3]};
                    uint32_t bll[2] = {bl_[0], bl_[2]}, blh[2] = {bl_[1], bl_[3]};
                    mma_16816(sacc[2 * bn4],     qfh[ks], bhl);
                    mma_16816(sacc[2 * bn4 + 1], qfh[ks], bhh);
                    mma_16816(sacc[2 * bn4],     qfh[ks], bll);
                    mma_16816(sacc[2 * bn4 + 1], qfh[ks], blh);
                    mma_16816(sacc[2 * bn4],     qfl[ks], bhl);
                    mma_16816(sacc[2 * bn4 + 1], qfl[ks], bhh);
                }
            }
        }

        if (j == jmax) {   // diagonal tile
            int r0 = q0 + wid * 16 + g2;
            #pragma unroll
            for (int bn = 0; bn < 8; ++bn) {
                int col = j * 64 + bn * 8 + 2 * t4;
                #pragma unroll
                for (int c = 0; c < 4; ++c) {
                    int row = r0 + ((c >= 2) ? 8 : 0);
                    if (col + (c & 1) > row) sacc[bn][c] = -1e30f;
                }
            }
        }

        float tm0 = -1e30f, tm1 = -1e30f;
        #pragma unroll
        for (int bn = 0; bn < 8; ++bn) {
            tm0 = fmaxf(tm0, fmaxf(sacc[bn][0], sacc[bn][1]));
            tm1 = fmaxf(tm1, fmaxf(sacc[bn][2], sacc[bn][3]));
        }
        tm0 = fmaxf(tm0, __shfl_xor_sync(0xffffffffu, tm0, 1));
        tm0 = fmaxf(tm0, __shfl_xor_sync(0xffffffffu, tm0, 2));
        tm1 = fmaxf(tm1, __shfl_xor_sync(0xffffffffu, tm1, 1));
        tm1 = fmaxf(tm1, __shfl_xor_sync(0xffffffffu, tm1, 2));
        float mn0 = fmaxf(m0, tm0), mn1 = fmaxf(m1, tm1);
        float sc0 = exp2f(m0 - mn0), sc1 = exp2f(m1 - mn1);
        float rs0 = 0.f, rs1 = 0.f;
        #pragma unroll
        for (int bn = 0; bn < 8; ++bn) {
            sacc[bn][0] = exp2f(sacc[bn][0] - mn0);
            sacc[bn][1] = exp2f(sacc[bn][1] - mn0);
            sacc[bn][2] = exp2f(sacc[bn][2] - mn1);
            sacc[bn][3] = exp2f(sacc[bn][3] - mn1);
            rs0 += sacc[bn][0] + sacc[bn][1];
            rs1 += sacc[bn][2] + sacc[bn][3];
        }
        rs0 += __shfl_xor_sync(0xffffffffu, rs0, 1);
        rs0 += __shfl_xor_sync(0xffffffffu, rs0, 2);
        rs1 += __shfl_xor_sync(0xffffffffu, rs1, 1);
        rs1 += __shfl_xor_sync(0xffffffffu, rs1, 2);
        l0 = l0 * sc0 + rs0;
        l1 = l1 * sc1 + rs1;
        m0 = mn0; m1 = mn1;
        #pragma unroll
        for (int bn = 0; bn < 8; ++bn) {
            oacc[bn][0] *= sc0; oacc[bn][1] *= sc0;
            oacc[bn][2] *= sc1; oacc[bn][3] *= sc1;
        }

        // O += Phi*Vhi + Phi*Vlo + Plo*Vhi
        {
            uint32_t vhB = sb + oVh + (uint32_t)(cur * 8192);
            uint32_t vlB = sb + oVl + (uint32_t)(cur * 8192);
            #pragma unroll
            for (int ks = 0; ks < 4; ++ks) {
                uint32_t ah[4], al[4];
                #pragma unroll
                for (int q = 0; q < 4; ++q) {
                    int tl = 2 * ks + (q >> 1);
                    int c0 = (q & 1) * 2;
                    split2(sacc[tl][c0], sacc[tl][c0 + 1], ah[q], al[q]);
                }
                uint32_t kbyte = (uint32_t)(ks * 32 + lkoff);
                #pragma unroll
                for (int bn4 = 0; bn4 < 4; ++bn4) {
                    uint32_t bH[4], bL[4];
                    uint32_t off = SW128((uint32_t)((bn4 * 16 + lrow) * 128) + kbyte);
                    ldm_x4(bH, vhB + off);
                    ldm_x4(bL, vlB + off);
                    uint32_t bHl[2] = {bH[0], bH[2]}, bHh[2] = {bH[1], bH[3]};
                    uint32_t bLl[2] = {bL[0], bL[2]}, bLh[2] = {bL[1], bL[3]};
                    mma_16816(oacc[2 * bn4],     ah, bHl);
                    mma_16816(oacc[2 * bn4 + 1], ah, bHh);
                    mma_16816(oacc[2 * bn4],     ah, bLl);
                    mma_16816(oacc[2 * bn4 + 1], ah, bLh);
                    mma_16816(oacc[2 * bn4],     al, bHl);
                    mma_16816(oacc[2 * bn4 + 1], al, bHh);
                }
            }
        }
    }

    float il0 = 1.f / l0, il1 = 1.f / l1;
    int row0 = q0 + wid * 16 + g2;
    size_t n0 = (size_t)b * Sv + row0;
    #pragma unroll
    for (int bn = 0; bn < 8; ++bn) {
        int col = h * 64 + bn * 8 + 2 * t4;
        #pragma unroll
        for (int half = 0; half < 2; ++half) {
            float v0 = oacc[bn][half * 2]     * (half ? il1 : il0);
            float v1 = oacc[bn][half * 2 + 1] * (half ? il1 : il0);
            uint32_t hp, lp;
            split2(v0, v1, hp, lp);
            size_t base = (n0 + half * 8) * Dv + col;
            *(uint32_t*)(g_ash + base) = hp;
            *(uint32_t*)(g_asl + base) = lp;
        }
    }
}

// ---------------------------------------------------------------------------
extern "C" void kernel_launch(void* const* d_in, const int* in_sizes, int n_in,
                              void* d_out, int out_size)
{
    const float* x  = (const float*)d_in[0];
    const int*   tp = (const int*)d_in[1];
    const float* w0 = (const float*)d_in[2];
    const float* w1 = (const float*)d_in[3];
    const float* w2 = (const float*)d_in[4];
    const float* w3 = (const float*)d_in[5];
    float* out = (float*)d_out;

    const int gemm_smem = 3 * 32768 + 1024;   // 97 KB -> 2 CTAs/SM
    cudaFuncSetAttribute(gemm_qkv, cudaFuncAttributeMaxDynamicSharedMemorySize,
                         gemm_smem);
    cudaFuncSetAttribute(gemm_o, cudaFuncAttributeMaxDynamicSharedMemorySize,
                         gemm_smem);
    const int attn_smem = 64 * 1024 + 1024;   // KV double buffers
    cudaFuncSetAttribute(attn_mma, cudaFuncAttributeMaxDynamicSharedMemorySize,
                         attn_smem);

    // 1) input/weight splits (hi/lo stored separately)
    xsplit_kernel<<<(Nv * Dv) / (4 * 256), 256>>>(x);
    wsplit_kernel<<<4 * (Dv * Dv) / (4 * 256), 256>>>(w0, w1, w2, w3);

    // 2) fused QKV projection; V epilogue writes transposed [bh][dk][s]
    gemm_qkv<<<dim3(24, Nv / 128), 256, gemm_smem>>>(tp);

    // 3) attention: 128-thread CTAs, q-tile 64 -> 2 CTAs/SM
    attn_mma<<<dim3(Sv / 64, Hv, Bv), 128, attn_smem>>>();

    // 4) output projection
    gemm_o<<<dim3(Dv / 128, Nv / 128), 256, gemm_smem>>>(out);
}

// round 17
// speedup vs baseline: 1.0861x; 1.0031x over previous
#include <cuda_runtime.h>
#include <cuda_bf16.h>
#include <math.h>
#include <stdint.h>

// Problem constants
#define Bv 2
#define Sv 2048
#define Dv 1024
#define Hv 16
#define DKv 64
#define Nv (Bv * Sv)     // 4096 rows
#define BHv (Bv * Hv)    // 32
#define NSLAB 48         // 3 terms x 16 K-chunks of 64

// ---------------------------------------------------------------------------
// Scratch (device globals — no cudaMalloc allowed). Hi/lo stored separately.
// ---------------------------------------------------------------------------
__device__ __nv_bfloat16 g_xh[(size_t)Nv * Dv];
__device__ __nv_bfloat16 g_xl[(size_t)Nv * Dv];
__device__ __nv_bfloat16 g_ash[(size_t)Nv * Dv];   // attention out hi
__device__ __nv_bfloat16 g_asl[(size_t)Nv * Dv];   // attention out lo
__device__ __nv_bfloat16 g_wh[4][(size_t)Dv * Dv];
__device__ __nv_bfloat16 g_wl[4][(size_t)Dv * Dv];
__device__ __nv_bfloat16 g_qh[(size_t)BHv * Sv * DKv];    // [bh][s][dk]
__device__ __nv_bfloat16 g_ql[(size_t)BHv * Sv * DKv];
__device__ __nv_bfloat16 g_kh[(size_t)BHv * Sv * DKv];
__device__ __nv_bfloat16 g_kl[(size_t)BHv * Sv * DKv];
__device__ __nv_bfloat16 g_vh[(size_t)BHv * DKv * Sv];    // [bh][dk][s]
__device__ __nv_bfloat16 g_vl[(size_t)BHv * DKv * Sv];

__device__ __forceinline__ uint32_t smem_to_u32(const void* p) {
    uint32_t a;
    asm("{ .reg .u64 t; cvta.to.shared.u64 t, %1; cvt.u32.u64 %0, t; }"
        : "=r"(a) : "l"(p));
    return a;
}
#define SW128(off) ((off) ^ (((off) >> 3) & 0x70))

__device__ __forceinline__ void ldm_x4(uint32_t* r, uint32_t addr) {
    asm volatile("ldmatrix.sync.aligned.m8n8.x4.shared.b16 {%0,%1,%2,%3}, [%4];"
        : "=r"(r[0]), "=r"(r[1]), "=r"(r[2]), "=r"(r[3]) : "r"(addr));
}
__device__ __forceinline__ void mma_16816(float* d, const uint32_t* a,
                                          const uint32_t* b) {
    asm volatile(
        "mma.sync.aligned.m16n8k16.row.col.f32.bf16.bf16.f32 "
        "{%0,%1,%2,%3}, {%4,%5,%6,%7}, {%8,%9}, {%0,%1,%2,%3};"
        : "+f"(d[0]), "+f"(d[1]), "+f"(d[2]), "+f"(d[3])
        : "r"(a[0]), "r"(a[1]), "r"(a[2]), "r"(a[3]), "r"(b[0]), "r"(b[1]));
}
__device__ __forceinline__ void cpa16(uint32_t dst, const void* src) {
    asm volatile("cp.async.cg.shared.global [%0], [%1], 16;"
        :: "r"(dst), "l"(src));
}
#define CP_COMMIT() asm volatile("cp.async.commit_group;" ::: "memory")
#define CP_WAIT(n)  asm volatile("cp.async.wait_group %0;" :: "n"(n) : "memory")

// split a float pair into hi/lo bf16x2 words
__device__ __forceinline__ void split2(float a, float b, uint32_t& h, uint32_t& l) {
    __nv_bfloat162 hp = __floats2bfloat162_rn(a, b);
    float r0 = __bfloat162float(hp.x), r1 = __bfloat162float(hp.y);
    __nv_bfloat162 lp = __floats2bfloat162_rn(a - r0, b - r1);
    h = *(uint32_t*)&hp;
    l = *(uint32_t*)&lp;
}

// ---------------------------------------------------------------------------
// Fused split: x (4096 blocks) + 4 weights (1024 blocks each) in ONE launch.
// ---------------------------------------------------------------------------
__global__ __launch_bounds__(256) void split_all(
    const float* __restrict__ x,
    const float* __restrict__ w0, const float* __restrict__ w1,
    const float* __restrict__ w2, const float* __restrict__ w3)
{
    int bid = blockIdx.x;
    const float* src;
    __nv_bfloat16 *dh, *dl;
    size_t e0;
    if (bid < 4096) {
        src = x; dh = g_xh; dl = g_xl;
        e0 = ((size_t)bid * 256 + threadIdx.x) * 4;
    } else {
        int i = (bid - 4096) >> 10;
        src = (i == 0) ? w0 : (i == 1) ? w1 : (i == 2) ? w2 : w3;
        dh = g_wh[i]; dl = g_wl[i];
        e0 = (((size_t)(bid - 4096) & 1023) * 256 + threadIdx.x) * 4;
    }
    float4 v = *(const float4*)(src + e0);
    uint2 hu, lu;
    split2(v.x, v.y, hu.x, lu.x);
    split2(v.z, v.w, hu.y, lu.y);
    *(uint2*)(dh + e0) = hu;
    *(uint2*)(dl + e0) = lu;
}

// ---------------------------------------------------------------------------
// GEMM: 128x128 CTA tile, 48 slabs of K=64 (unchanged, proven).
// mode: 0 = fp32 store; 1 = K RoPE split; 2 = Q RoPE*(0.125*log2e) split;
//       3 = V split written TRANSPOSED [bh][dk][s].
// ---------------------------------------------------------------------------
__device__ __forceinline__ void gemm_load_slab(
    const __nv_bfloat16* __restrict__ Ah, const __nv_bfloat16* __restrict__ Al,
    const __nv_bfloat16* __restrict__ Bh, const __nv_bfloat16* __restrict__ Bl,
    uint32_t bufu, int s, int tid)
{
    const int t = s >> 4;
    const int k = s & 15;
    const __nv_bfloat16* As = (t == 2) ? Al : Ah;
    const __nv_bfloat16* Bs = (t == 1) ? Bl : Bh;
    #pragma unroll
    for (int kk = 0; kk < 4; ++kk) {
        int idx = kk * 256 + tid;
        int r = idx >> 3, c = idx & 7;
        size_t goff = (size_t)r * Dv + k * 64 + c * 8;
        uint32_t so = SW128((uint32_t)(r * 128 + c * 16));
        cpa16(bufu + so,         As + goff);
        cpa16(bufu + 16384 + so, Bs + goff);
    }
}

__device__ __forceinline__ void gemm_tile(
    const __nv_bfloat16* __restrict__ Ah, const __nv_bfloat16* __restrict__ Al,
    const __nv_bfloat16* __restrict__ Bh, const __nv_bfloat16* __restrict__ Bl,
    const int* __restrict__ tp, int mode, int m0, int e0, uint32_t sbu,
    float* __restrict__ Y, __nv_bfloat16* __restrict__ dh,
    __nv_bfloat16* __restrict__ dl)
{
    const int tid = threadIdx.x;
    const int wid = tid >> 5;
    const int lane = tid & 31;
    const int wm = wid >> 1;
    const int wn = wid & 1;
    const int g2 = lane >> 2;
    const int t4 = lane & 3;
    const int lrow = lane & 15;
    const int lkoff = ((lane >> 4) & 1) * 16;

    float acc[2][8][4];
    #pragma unroll
    for (int i = 0; i < 2; ++i)
        #pragma unroll
        for (int j = 0; j < 8; ++j)
            #pragma unroll
            for (int k = 0; k < 4; ++k) acc[i][j][k] = 0.f;

    gemm_load_slab(Ah, Al, Bh, Bl, sbu, 0, tid);
    CP_COMMIT();
    gemm_load_slab(Ah, Al, Bh, Bl, sbu + 32768, 1, tid);
    CP_COMMIT();

    int cc = 0;
    for (int s = 0; s < NSLAB; ++s) {
        if (s + 1 < NSLAB) { CP_WAIT(1); } else { CP_WAIT(0); }
        __syncthreads();
        if (s + 2 < NSLAB) {
            int nb = cc + 2; if (nb >= 3) nb -= 3;
            gemm_load_slab(Ah, Al, Bh, Bl, sbu + (uint32_t)(nb * 32768),
                           s + 2, tid);
            CP_COMMIT();
        }

        const uint32_t pAu = sbu + (uint32_t)(cc * 32768);
        const uint32_t pBu = pAu + 16384;
        #pragma unroll
        for (int ks = 0; ks < 4; ++ks) {
            const uint32_t kbyte = (uint32_t)(ks * 32 + lkoff);
            uint32_t afr[2][4], bfr[4][4];
            #pragma unroll
            for (int am = 0; am < 2; ++am) {
                uint32_t off = (uint32_t)((wm * 32 + am * 16 + lrow) * 128) + kbyte;
                ldm_x4(afr[am], pAu + SW128(off));
            }
            #pragma unroll
            for (int bn = 0; bn < 4; ++bn) {
                uint32_t off = (uint32_t)((wn * 64 + bn * 16 + lrow) * 128) + kbyte;
                ldm_x4(bfr[bn], pBu + SW128(off));
            }
            #pragma unroll
            for (int am = 0; am < 2; ++am)
                #pragma unroll
                for (int bn = 0; bn < 4; ++bn) {
                    uint32_t blo[2] = {bfr[bn][0], bfr[bn][2]};
                    uint32_t bhi[2] = {bfr[bn][1], bfr[bn][3]};
                    mma_16816(acc[am][bn * 2],     afr[am], blo);
                    mma_16816(acc[am][bn * 2 + 1], afr[am], bhi);
                }
        }
        ++cc; if (cc == 3) cc = 0;
    }

    // Q scale folds 1/sqrt(64) and log2(e) so attention can use exp2f.
    const float qs = (mode == 2) ? 0.18033688011112042f : 1.0f;
    const float LTH = 0.2878231366242557f;   // ln(10000)/32
    #pragma unroll
    for (int am = 0; am < 2; ++am) {
        #pragma unroll
        for (int half = 0; half < 2; ++half) {
            int m = m0 + wm * 32 + am * 16 + g2 + half * 8;
            int sr = m & (Sv - 1);
            float pos = (mode == 1 || mode == 2) ? (float)tp[sr] : 0.f;
            #pragma unroll
            for (int bn = 0; bn < 8; ++bn) {
                int e = e0 + wn * 64 + bn * 8 + t4 * 2;
                float d0 = acc[am][bn][half * 2];
                float d1 = acc[am][bn][half * 2 + 1];
                if (mode == 1 || mode == 2) {
                    int p = (e & (DKv - 1)) >> 1;
                    float inv = expf(-LTH * (float)p);
                    float sn, cs;
                    sincosf(pos * inv, &sn, &cs);
                    float o0 = (cs * d0 - sn * d1) * qs;
                    float o1 = (sn * d0 + cs * d1) * qs;
                    d0 = o0; d1 = o1;
                }
                if (mode == 0) {
                    *(float2*)(Y + (size_t)m * Dv + e) = make_float2(d0, d1);
                } else if (mode == 3) {
                    int bh = (m >> 11) * Hv + (e >> 6);
                    int dk = e & (DKv - 1);
                    size_t idx = ((size_t)bh * DKv + dk) * Sv + sr;
                    uint32_t h, l;
                    split2(d0, d1, h, l);
                    *(uint16_t*)((uint16_t*)g_vh + idx)      = (uint16_t)h;
                    *(uint16_t*)((uint16_t*)g_vh + idx + Sv) = (uint16_t)(h >> 16);
                    *(uint16_t*)((uint16_t*)g_vl + idx)      = (uint16_t)l;
                    *(uint16_t*)((uint16_t*)g_vl + idx + Sv) = (uint16_t)(l >> 16);
                } else {
                    int bh = (m >> 11) * Hv + (e >> 6);
                    int dk = e & (DKv - 1);
                    size_t idx = ((size_t)bh * Sv + sr) * DKv + dk;
                    uint32_t h, l;
                    split2(d0, d1, h, l);
                    *(uint32_t*)(dh + idx) = h;
                    *(uint32_t*)(dl + idx) = l;
                }
            }
        }
    }
}

// Fused QKV projection: grid (24, 32); region = blockIdx.x >> 3 (0=Q,1=K,2=V)
__global__ __launch_bounds__(256, 2) void gemm_qkv(const int* __restrict__ tp)
{
    extern __shared__ char smraw[];
    uint32_t su = smem_to_u32(smraw);
    uint32_t sbu = (su + 1023u) & ~1023u;

    const int region = blockIdx.x >> 3;
    const int e0 = (blockIdx.x & 7) * 128;
    const int m0 = blockIdx.y * 128;
    const __nv_bfloat16* Ah = g_xh + (size_t)m0 * Dv;
    const __nv_bfloat16* Al = g_xl + (size_t)m0 * Dv;
    const __nv_bfloat16* Bh = g_wh[region] + (size_t)e0 * Dv;
    const __nv_bfloat16* Bl = g_wl[region] + (size_t)e0 * Dv;
    __nv_bfloat16* dh = (region == 0) ? g_qh : g_kh;
    __nv_bfloat16* dl = (region == 0) ? g_ql : g_kl;
    const int mode = (region == 0) ? 2 : (region == 1) ? 1 : 3;
    gemm_tile(Ah, Al, Bh, Bl, tp, mode, m0, e0, sbu, (float*)0, dh, dl);
}

// Output projection: grid (8, 32)
__global__ __launch_bounds__(256, 2) void gemm_o(float* __restrict__ out)
{
    extern __shared__ char smraw[];
    uint32_t su = smem_to_u32(smraw);
    uint32_t sbu = (su + 1023u) & ~1023u;

    const int e0 = blockIdx.x * 128;
    const int m0 = blockIdx.y * 128;
    gemm_tile(g_ash + (size_t)m0 * Dv, g_asl + (size_t)m0 * Dv,
              g_wh[3] + (size_t)e0 * Dv, g_wl[3] + (size_t)e0 * Dv,
              (const int*)0, 0, m0, e0, sbu, out,
              (__nv_bfloat16*)0, (__nv_bfloat16*)0);
}

// ---------------------------------------------------------------------------
// Flash attention on mma.sync, 3-term split for QK^T and PV, exp2f softmax.
// CTA = 128 threads, q-tile 64 rows -> 2 CTAs/SM. KV tiles 64, double-buffered.
// Q staged in buf-1 smem slots so tile-0 KV load overlaps the Q load.
// ---------------------------------------------------------------------------
__device__ __forceinline__ void attn_load_tile(
    uint32_t sb, int bh, int j, int buf, int tid)
{
    const uint32_t oKh = 0, oKl = 16384, oVh = 32768, oVl = 49152;
    const char* kh = (const char*)(g_kh + ((size_t)bh * Sv + j * 64) * 64);
    const char* kl = (const char*)(g_kl + ((size_t)bh * Sv + j * 64) * 64);
    #pragma unroll
    for (int p = 0; p < 4; ++p) {
        int idx = p * 128 + tid;      // 0..511 chunks of 16B
        int r = idx >> 3, c = idx & 7;
        uint32_t so = SW128((uint32_t)(r * 128 + c * 16));
        uint32_t bo = (uint32_t)(buf * 8192);
        cpa16(sb + oKh + bo + so, kh + idx * 16);
        cpa16(sb + oKl + bo + so, kl + idx * 16);
        const char* vh = (const char*)(g_vh + ((size_t)bh * 64 + r) * Sv + j * 64);
        const char* vl = (const char*)(g_vl + ((size_t)bh * 64 + r) * Sv + j * 64);
        cpa16(sb + oVh + bo + so, vh + c * 16);
        cpa16(sb + oVl + bo + so, vl + c * 16);
    }
}

__global__ __launch_bounds__(128, 1) void attn_mma()
{
    extern __shared__ char smraw[];
    uint32_t su = smem_to_u32(smraw);
    uint32_t sb = (su + 1023u) & ~1023u;
    const uint32_t oKh = 0, oKl = 16384, oVh = 32768, oVl = 49152;

    const int tid = threadIdx.x;
    const int wid = tid >> 5, lane = tid & 31;
    const int g2 = lane >> 2, t4 = lane & 3;
    const int lrow = lane & 15;
    const int lkoff = ((lane >> 4) & 1) * 16;

    const int qt = gridDim.x - 1 - blockIdx.x;   // big tiles first
    const int h = blockIdx.y, b = blockIdx.z;
    const int bh = b * Hv + h;
    const int q0 = qt * 64;
    const int jmax = qt;

    // --- prologue: Q staged in buf-1 slots (8K..16K, 24K..32K) so the KV
    // tile-0 load (buf-0 slots) overlaps it. Group order: Q older, KV0 newer.
    uint32_t qfh[4][4], qfl[4][4];
    {
        const char* qh = (const char*)(g_qh + ((size_t)bh * Sv + q0) * 64);
        const char* ql = (const char*)(g_ql + ((size_t)bh * Sv + q0) * 64);
        #pragma unroll
        for (int p = 0; p < 4; ++p) {
            int idx = p * 128 + tid;   // 0..511 chunks (64x64 bf16 = 8KB)
            uint32_t so = SW128((uint32_t)(idx * 16));
            cpa16(sb + 8192  + so, qh + idx * 16);
            cpa16(sb + 24576 + so, ql + idx * 16);
        }
        CP_COMMIT();                       // group: Q
        attn_load_tile(sb, bh, 0, 0, tid);
        CP_COMMIT();                       // group: KV tile 0
        CP_WAIT(1);                        // Q landed (KV0 may still fly)
        __syncthreads();
        #pragma unroll
        for (int ks = 0; ks < 4; ++ks) {
            uint32_t aoff =
                SW128((uint32_t)((wid * 16 + lrow) * 128 + ks * 32 + lkoff));
            ldm_x4(qfh[ks], sb + 8192  + aoff);
            ldm_x4(qfl[ks], sb + 24576 + aoff);
        }
        // loop's first CP_WAIT(0)+sync orders tile-1 writes after these reads
    }

    float m0 = -1e30f, m1 = -1e30f, l0 = 0.f, l1 = 0.f;
    float oacc[8][4];
    #pragma unroll
    for (int i = 0; i < 8; ++i)
        #pragma unroll
        for (int c = 0; c < 4; ++c) oacc[i][c] = 0.f;

    for (int j = 0; j <= jmax; ++j) {
        const int cur = j & 1;
        CP_WAIT(0);
        __syncthreads();
        if (j < jmax) {
            attn_load_tile(sb, bh, j + 1, cur ^ 1, tid);
            CP_COMMIT();
        }

        // S = Qhi*Khi + Qhi*Klo + Qlo*Khi (Q frags in regs)
        float sacc[8][4];
        #pragma unroll
        for (int i = 0; i < 8; ++i)
            #pragma unroll
            for (int c = 0; c < 4; ++c) sacc[i][c] = 0.f;
        {
            const uint32_t kb = (uint32_t)(cur * 8192);
            const uint32_t khB = sb + oKh + kb, klB = sb + oKl + kb;
            #pragma unroll
            for (int ks = 0; ks < 4; ++ks) {
                uint32_t kbyte = (uint32_t)(ks * 32 + lkoff);
                #pragma unroll
                for (int bn4 = 0; bn4 < 4; ++bn4) {
                    uint32_t boff = SW128((uint32_t)((bn4 * 16 + lrow) * 128) + kbyte);
                    uint32_t bh_[4], bl_[4];
                    ldm_x4(bh_, khB + boff);
                    ldm_x4(bl_, klB + boff);
                    uint32_t bhl[2] = {bh_[0], bh_[2]}, bhh[2] = {bh_[1], bh_[3]};
                    uint32_t bll[2] = {bl_[0], bl_[2]}, blh[2] = {bl_[1], bl_[3]};
                    mma_16816(sacc[2 * bn4],     qfh[ks], bhl);
                    mma_16816(sacc[2 * bn4 + 1], qfh[ks], bhh);
                    mma_16816(sacc[2 * bn4],     qfh[ks], bll);
                    mma_16816(sacc[2 * bn4 + 1], qfh[ks], blh);
                    mma_16816(sacc[2 * bn4],     qfl[ks], bhl);
                    mma_16816(sacc[2 * bn4 + 1], qfl[ks], bhh);
                }
            }
        }

        if (j == jmax) {   // diagonal tile
            int r0 = q0 + wid * 16 + g2;
            #pragma unroll
            for (int bn = 0; bn < 8; ++bn) {
                int col = j * 64 + bn * 8 + 2 * t4;
                #pragma unroll
                for (int c = 0; c < 4; ++c) {
                    int row = r0 + ((c >= 2) ? 8 : 0);
                    if (col + (c & 1) > row) sacc[bn][c] = -1e30f;
                }
            }
        }

        float tm0 = -1e30f, tm1 = -1e30f;
        #pragma unroll
        for (int bn = 0; bn < 8; ++bn) {
            tm0 = fmaxf(tm0, fmaxf(sacc[bn][0], sacc[bn][1]));
            tm1 = fmaxf(tm1, fmaxf(sacc[bn][2], sacc[bn][3]));
        }
        tm0 = fmaxf(tm0, __shfl_xor_sync(0xffffffffu, tm0, 1));
        tm0 = fmaxf(tm0, __shfl_xor_sync(0xffffffffu, tm0, 2));
        tm1 = fmaxf(tm1, __shfl_xor_sync(0xffffffffu, tm1, 1));
        tm1 = fmaxf(tm1, __shfl_xor_sync(0xffffffffu, tm1, 2));
        float mn0 = fmaxf(m0, tm0), mn1 = fmaxf(m1, tm1);

        // warp-uniform rescale skip: exp2f(0)==1 exactly, so skipping the
        // multiplies when no row raised its max is bit-identical.
        const bool stable =
            __all_sync(0xffffffffu, (mn0 == m0) && (mn1 == m1));
        if (!stable) {
            float sc0 = exp2f(m0 - mn0), sc1 = exp2f(m1 - mn1);
            l0 *= sc0; l1 *= sc1;
            #pragma unroll
            for (int bn = 0; bn < 8; ++bn) {
                oacc[bn][0] *= sc0; oacc[bn][1] *= sc0;
                oacc[bn][2] *= sc1; oacc[bn][3] *= sc1;
            }
            m0 = mn0; m1 = mn1;
        }

        float rs0 = 0.f, rs1 = 0.f;
        #pragma unroll
        for (int bn = 0; bn < 8; ++bn) {
            sacc[bn][0] = exp2f(sacc[bn][0] - m0);
            sacc[bn][1] = exp2f(sacc[bn][1] - m0);
            sacc[bn][2] = exp2f(sacc[bn][2] - m1);
            sacc[bn][3] = exp2f(sacc[bn][3] - m1);
            rs0 += sacc[bn][0] + sacc[bn][1];
            rs1 += sacc[bn][2] + sacc[bn][3];
        }
        rs0 += __shfl_xor_sync(0xffffffffu, rs0, 1);
        rs0 += __shfl_xor_sync(0xffffffffu, rs0, 2);
        rs1 += __shfl_xor_sync(0xffffffffu, rs1, 1);
        rs1 += __shfl_xor_sync(0xffffffffu, rs1, 2);
        l0 += rs0;
        l1 += rs1;

        // O += Phi*Vhi + Phi*Vlo + Plo*Vhi
        {
            uint32_t vhB = sb + oVh + (uint32_t)(cur * 8192);
            uint32_t vlB = sb + oVl + (uint32_t)(cur * 8192);
            #pragma unroll
            for (int ks = 0; ks < 4; ++ks) {
                uint32_t ah[4], al[4];
                #pragma unroll
                for (int q = 0; q < 4; ++q) {
                    int tl = 2 * ks + (q >> 1);
                    int c0 = (q & 1) * 2;
                    split2(sacc[tl][c0], sacc[tl][c0 + 1], ah[q], al[q]);
                }
                uint32_t kbyte = (uint32_t)(ks * 32 + lkoff);
                #pragma unroll
                for (int bn4 = 0; bn4 < 4; ++bn4) {
                    uint32_t bH[4], bL[4];
                    uint32_t off = SW128((uint32_t)((bn4 * 16 + lrow) * 128) + kbyte);
                    ldm_x4(bH, vhB + off);
                    ldm_x4(bL, vlB + off);
                    uint32_t bHl[2] = {bH[0], bH[2]}, bHh[2] = {bH[1], bH[3]};
                    uint32_t bLl[2] = {bL[0], bL[2]}, bLh[2] = {bL[1], bL[3]};
                    mma_16816(oacc[2 * bn4],     ah, bHl);
                    mma_16816(oacc[2 * bn4 + 1], ah, bHh);
                    mma_16816(oacc[2 * bn4],     ah, bLl);
                    mma_16816(oacc[2 * bn4 + 1], ah, bLh);
                    mma_16816(oacc[2 * bn4],     al, bHl);
                    mma_16816(oacc[2 * bn4 + 1], al, bHh);
                }
            }
        }
    }

    float il0 = 1.f / l0, il1 = 1.f / l1;
    int row0 = q0 + wid * 16 + g2;
    size_t n0 = (size_t)b * Sv + row0;
    #pragma unroll
    for (int bn = 0; bn < 8; ++bn) {
        int col = h * 64 + bn * 8 + 2 * t4;
        #pragma unroll
        for (int half = 0; half < 2; ++half) {
            float v0 = oacc[bn][half * 2]     * (half ? il1 : il0);
            float v1 = oacc[bn][half * 2 + 1] * (half ? il1 : il0);
            uint32_t hp, lp;
            split2(v0, v1, hp, lp);
            size_t base = (n0 + half * 8) * Dv + col;
            *(uint32_t*)(g_ash + base) = hp;
            *(uint32_t*)(g_asl + base) = lp;
        }
    }
}

// ---------------------------------------------------------------------------
extern "C" void kernel_launch(void* const* d_in, const int* in_sizes, int n_in,
                              void* d_out, int out_size)
{
    const float* x  = (const float*)d_in[0];
    const int*   tp = (const int*)d_in[1];
    const float* w0 = (const float*)d_in[2];
    const float* w1 = (const float*)d_in[3];
    const float* w2 = (const float*)d_in[4];
    const float* w3 = (const float*)d_in[5];
    float* out = (float*)d_out;

    const int gemm_smem = 3 * 32768 + 1024;   // 97 KB -> 2 CTAs/SM
    cudaFuncSetAttribute(gemm_qkv, cudaFuncAttributeMaxDynamicSharedMemorySize,
                         gemm_smem);
    cudaFuncSetAttribute(gemm_o, cudaFuncAttributeMaxDynamicSharedMemorySize,
                         gemm_smem);
    const int attn_smem = 64 * 1024 + 1024;   // KV double buffers
    cudaFuncSetAttribute(attn_mma, cudaFuncAttributeMaxDynamicSharedMemorySize,
                         attn_smem);

    // 1) fused input/weight splits (one launch)
    split_all<<<4096 + 4 * 1024, 256>>>(x, w0, w1, w2, w3);

    // 2) fused QKV projection; V epilogue writes transposed [bh][dk][s]
    gemm_qkv<<<dim3(24, Nv / 128), 256, gemm_smem>>>(tp);

    // 3) attention: 128-thread CTAs, q-tile 64 -> 2 CTAs/SM
    attn_mma<<<dim3(Sv / 64, Hv, Bv), 128, attn_smem>>>();

    // 4) output projection
    gemm_o<<<dim3(Dv / 128, Nv / 128), 256, gemm_smem>>>(out);
}